// round 4
// baseline (speedup 1.0000x reference)
#include <cuda_runtime.h>
#include <cuda_bf16.h>
#include <cstdint>
#include <cmath>

#define NTOK 8192
#define DDIM 1024

// Scratch (allocation-free rule: __device__ globals)
__device__ float g_Q[(size_t)NTOK * DDIM];
__device__ float g_K[(size_t)NTOK * DDIM];
__device__ float g_V[(size_t)NTOK * DDIM];
__device__ float g_S[(size_t)NTOK * NTOK];

// Pack two floats' bf16-hi parts / bf16-lo (residual) parts into b32 words.
__device__ __forceinline__ void split_pack2(float x, float y, uint32_t& hi, uint32_t& lo) {
    __nv_bfloat162 h = __floats2bfloat162_rn(x, y);          // .x = x (low half = even k)
    float rx = x - __bfloat162float(h.x);
    float ry = y - __bfloat162float(h.y);
    __nv_bfloat162 l = __floats2bfloat162_rn(rx, ry);
    hi = *reinterpret_cast<uint32_t*>(&h);
    lo = *reinterpret_cast<uint32_t*>(&l);
}

__device__ __forceinline__ void mma_bf16(float c[4], const uint32_t a[4], const uint32_t b[2]) {
    asm volatile(
        "mma.sync.aligned.m16n8k16.row.col.f32.bf16.bf16.f32 "
        "{%0,%1,%2,%3}, {%4,%5,%6,%7}, {%8,%9}, {%0,%1,%2,%3};\n"
        : "+f"(c[0]), "+f"(c[1]), "+f"(c[2]), "+f"(c[3])
        : "r"(a[0]), "r"(a[1]), "r"(a[2]), "r"(a[3]), "r"(b[0]), "r"(b[1]));
}

// C[M,Nn] = scale * A[M,Kk] @ B, fp32 in/out, bf16x2 split (3-term) tensor-core math.
// BT=false: B is [Kk,Nn] row-major (NN). BT=true: B is [Nn,Kk] row-major (NT).
// Requires M%128==0, Nn%128==0, Kk%32==0.
template <bool BT>
__global__ void __launch_bounds__(256) gemm_bf16x2(
    const float* __restrict__ A, const float* __restrict__ B, float* __restrict__ C,
    int M, int Nn, int Kk, float scale)
{
    // Word layout: each uint32 = two bf16 along k (even k in low half).
    // A: [row][kword], stride 20 -> conflict-free frag LDS (g*20+t pattern).
    // B: [kword][n],  stride 136 -> conflict-free frag LDS (t*136+g pattern).
    __shared__ uint32_t Ah[128][20], Al[128][20];
    __shared__ uint32_t Bh[16][136], Bl[16][136];

    const int t = threadIdx.x;
    const int bRow = blockIdx.y * 128;
    const int bCol = blockIdx.x * 128;
    const int warp = t >> 5, lane = t & 31;
    const int wm = warp & 1;   // 2 warps along M -> 64-row warp tile
    const int wn = warp >> 1;  // 4 warps along N -> 32-col warp tile
    const int g = lane >> 2, tq = lane & 3;

    // Per-thread load coordinates (fixed across k-tiles)
    const int aRow = (t >> 3);          // +p*32
    const int aK   = (t & 7) * 4;       // 4 consecutive k
    const int bnRow = (t >> 3);         // BT: n base (+p*32)
    const int bnK   = (t & 7) * 4;
    const int bkRow = (t >> 5);         // NN: k base (+p*8)
    const int bNq   = (t & 31) * 4;     // 4 consecutive n

    float acc[4][4][4];
#pragma unroll
    for (int i = 0; i < 4; ++i)
#pragma unroll
        for (int j = 0; j < 4; ++j)
#pragma unroll
            for (int k = 0; k < 4; ++k) acc[i][j][k] = 0.f;

    float4 aReg[4], bReg[4];

    // ---- prefetch tile 0 ----
#pragma unroll
    for (int p = 0; p < 4; ++p)
        aReg[p] = *(const float4*)(A + (size_t)(bRow + aRow + p * 32) * Kk + aK);
    if (BT) {
#pragma unroll
        for (int p = 0; p < 4; ++p)
            bReg[p] = *(const float4*)(B + (size_t)(bCol + bnRow + p * 32) * Kk + bnK);
    } else {
#pragma unroll
        for (int p = 0; p < 4; ++p)
            bReg[p] = *(const float4*)(B + (size_t)(bkRow + p * 8) * Nn + bCol + bNq);
    }

    for (int kt = 0; kt < Kk; kt += 32) {
        // ---- split + store current tile regs -> SMEM ----
#pragma unroll
        for (int p = 0; p < 4; ++p) {
            int row = aRow + p * 32;
            uint32_t h0, l0, h1, l1;
            split_pack2(aReg[p].x, aReg[p].y, h0, l0);
            split_pack2(aReg[p].z, aReg[p].w, h1, l1);
            Ah[row][(aK >> 1) + 0] = h0;  Al[row][(aK >> 1) + 0] = l0;
            Ah[row][(aK >> 1) + 1] = h1;  Al[row][(aK >> 1) + 1] = l1;
        }
        if (BT) {
#pragma unroll
            for (int p = 0; p < 4; ++p) {
                int n = bnRow + p * 32;
                uint32_t h0, l0, h1, l1;
                split_pack2(bReg[p].x, bReg[p].y, h0, l0);
                split_pack2(bReg[p].z, bReg[p].w, h1, l1);
                Bh[(bnK >> 1) + 0][n] = h0;  Bl[(bnK >> 1) + 0][n] = l0;
                Bh[(bnK >> 1) + 1][n] = h1;  Bl[(bnK >> 1) + 1][n] = l1;
            }
        } else {
#pragma unroll
            for (int p = 0; p < 4; ++p) {
                int k = bkRow + p * 8;
                const float v[4] = {bReg[p].x, bReg[p].y, bReg[p].z, bReg[p].w};
#pragma unroll
                for (int j = 0; j < 4; ++j) {
                    int n = bNq + j;
                    __nv_bfloat16 h = __float2bfloat16_rn(v[j]);
                    __nv_bfloat16 l = __float2bfloat16_rn(v[j] - __bfloat162float(h));
                    ((__nv_bfloat16*)&Bh[k >> 1][n])[k & 1] = h;
                    ((__nv_bfloat16*)&Bl[k >> 1][n])[k & 1] = l;
                }
            }
        }
        __syncthreads();

        // ---- prefetch next tile (overlapped by MMAs below) ----
        const int kn = kt + 32;
        if (kn < Kk) {
#pragma unroll
            for (int p = 0; p < 4; ++p)
                aReg[p] = *(const float4*)(A + (size_t)(bRow + aRow + p * 32) * Kk + kn + aK);
            if (BT) {
#pragma unroll
                for (int p = 0; p < 4; ++p)
                    bReg[p] = *(const float4*)(B + (size_t)(bCol + bnRow + p * 32) * Kk + kn + bnK);
            } else {
#pragma unroll
                for (int p = 0; p < 4; ++p)
                    bReg[p] = *(const float4*)(B + (size_t)(kn + bkRow + p * 8) * Nn + bCol + bNq);
            }
        }

        // ---- MMA: two k16 steps per 32-k tile, 3-term split product ----
#pragma unroll
        for (int ks2 = 0; ks2 < 16; ks2 += 8) {   // kword base: 0, 8
            uint32_t ah[4][4], al[4][4], bh[4][2], bl[4][2];
#pragma unroll
            for (int mt = 0; mt < 4; ++mt) {
                int r = wm * 64 + mt * 16 + g;
                int w = ks2 + tq;
                ah[mt][0] = Ah[r][w];     ah[mt][1] = Ah[r + 8][w];
                ah[mt][2] = Ah[r][w + 4]; ah[mt][3] = Ah[r + 8][w + 4];
                al[mt][0] = Al[r][w];     al[mt][1] = Al[r + 8][w];
                al[mt][2] = Al[r][w + 4]; al[mt][3] = Al[r + 8][w + 4];
            }
#pragma unroll
            for (int nt = 0; nt < 4; ++nt) {
                int c = wn * 32 + nt * 8 + g;
                int w = ks2 + tq;
                bh[nt][0] = Bh[w][c]; bh[nt][1] = Bh[w + 4][c];
                bl[nt][0] = Bl[w][c]; bl[nt][1] = Bl[w + 4][c];
            }
#pragma unroll
            for (int mt = 0; mt < 4; ++mt)
#pragma unroll
                for (int nt = 0; nt < 4; ++nt) {
                    mma_bf16(acc[mt][nt], ah[mt], bh[nt]);
                    mma_bf16(acc[mt][nt], ah[mt], bl[nt]);
                    mma_bf16(acc[mt][nt], al[mt], bh[nt]);
                }
        }
        __syncthreads();
    }

    // ---- epilogue ----
#pragma unroll
    for (int mt = 0; mt < 4; ++mt) {
#pragma unroll
        for (int nt = 0; nt < 4; ++nt) {
            int r = bRow + wm * 64 + mt * 16 + g;
            int c = bCol + wn * 32 + nt * 8 + tq * 2;
            float2 v0 = make_float2(acc[mt][nt][0] * scale, acc[mt][nt][1] * scale);
            float2 v1 = make_float2(acc[mt][nt][2] * scale, acc[mt][nt][3] * scale);
            *(float2*)(C + (size_t)r * Nn + c) = v0;
            *(float2*)(C + (size_t)(r + 8) * Nn + c) = v1;
        }
    }
}

// In-place row softmax over S[NTOK][NTOK]. One block per row.
__global__ void __launch_bounds__(256) softmax_rows(float* __restrict__ S) {
    __shared__ float buf[NTOK];   // 32 KB: full row
    __shared__ float red[8];
    const int row = blockIdx.x;
    const int t = threadIdx.x;
    float* rp = S + (size_t)row * NTOK;

    float lmax = -INFINITY;
#pragma unroll
    for (int i = 0; i < 8; ++i) {
        int idx = (i * 256 + t) * 4;
        float4 v = *(const float4*)(rp + idx);
        *(float4*)(buf + idx) = v;
        lmax = fmaxf(lmax, fmaxf(fmaxf(v.x, v.y), fmaxf(v.z, v.w)));
    }
#pragma unroll
    for (int o = 16; o; o >>= 1) lmax = fmaxf(lmax, __shfl_xor_sync(0xffffffffu, lmax, o));
    if ((t & 31) == 0) red[t >> 5] = lmax;
    __syncthreads();
    float m = red[0];
#pragma unroll
    for (int i = 1; i < 8; ++i) m = fmaxf(m, red[i]);
    __syncthreads();

    float lsum = 0.f;
#pragma unroll
    for (int i = 0; i < 8; ++i) {
        int idx = (i * 256 + t) * 4;
        float4 v = *(const float4*)(buf + idx);
        v.x = __expf(v.x - m);
        v.y = __expf(v.y - m);
        v.z = __expf(v.z - m);
        v.w = __expf(v.w - m);
        lsum += (v.x + v.y) + (v.z + v.w);
        *(float4*)(buf + idx) = v;
    }
#pragma unroll
    for (int o = 16; o; o >>= 1) lsum += __shfl_xor_sync(0xffffffffu, lsum, o);
    if ((t & 31) == 0) red[t >> 5] = lsum;
    __syncthreads();
    float s = red[0];
#pragma unroll
    for (int i = 1; i < 8; ++i) s += red[i];
    float inv = 1.f / s;

#pragma unroll
    for (int i = 0; i < 8; ++i) {
        int idx = (i * 256 + t) * 4;
        float4 v = *(const float4*)(buf + idx);
        v.x *= inv; v.y *= inv; v.z *= inv; v.w *= inv;
        *(float4*)(rp + idx) = v;
    }
}

extern "C" void kernel_launch(void* const* d_in, const int* in_sizes, int n_in,
                              void* d_out, int out_size)
{
    const float* x  = (const float*)d_in[0];
    const float* wq = (const float*)d_in[1];
    const float* wk = (const float*)d_in[2];
    const float* wv = (const float*)d_in[3];
    float* out = (float*)d_out;

    static float *Q = nullptr, *K = nullptr, *V = nullptr, *S = nullptr;
    if (!Q) {
        cudaGetSymbolAddress((void**)&Q, g_Q);
        cudaGetSymbolAddress((void**)&K, g_K);
        cudaGetSymbolAddress((void**)&V, g_V);
        cudaGetSymbolAddress((void**)&S, g_S);
    }

    // Projections: [8192,1024] @ [1024,1024]  (NN)
    dim3 gProj(DDIM / 128, NTOK / 128);
    gemm_bf16x2<false><<<gProj, 256>>>(x, wq, Q, NTOK, DDIM, DDIM, 1.f);
    gemm_bf16x2<false><<<gProj, 256>>>(x, wk, K, NTOK, DDIM, DDIM, 1.f);
    gemm_bf16x2<false><<<gProj, 256>>>(x, wv, V, NTOK, DDIM, DDIM, 1.f);

    // Scores: Q @ K^T * (1/sqrt(1024))  (NT)
    dim3 gScore(NTOK / 128, NTOK / 128);
    gemm_bf16x2<true><<<gScore, 256>>>(Q, K, S, NTOK, NTOK, DDIM, 0.03125f);

    // Row softmax in place
    softmax_rows<<<NTOK, 256>>>(S);

    // Output: P @ V  (NN)
    dim3 gOut(DDIM / 128, NTOK / 128);
    gemm_bf16x2<false><<<gOut, 256>>>(S, V, out, NTOK, DDIM, NTOK, 1.f);
}

// round 5
// speedup vs baseline: 1.0455x; 1.0455x over previous
#include <cuda_runtime.h>
#include <cuda_bf16.h>
#include <cstdint>
#include <cmath>

#define NTOK 8192
#define DDIM 1024

// Scratch (allocation-free rule: __device__ globals)
__device__ float g_Q[(size_t)NTOK * DDIM];
__device__ float g_K[(size_t)NTOK * DDIM];
__device__ float g_V[(size_t)NTOK * DDIM];
__device__ float g_S[(size_t)NTOK * NTOK];

// Pack two floats' bf16-hi parts / bf16-lo (residual) parts into b32 words.
__device__ __forceinline__ void split_pack2(float x, float y, uint32_t& hi, uint32_t& lo) {
    __nv_bfloat162 h = __floats2bfloat162_rn(x, y);          // .x = x (low half = even k)
    float rx = x - __bfloat162float(h.x);
    float ry = y - __bfloat162float(h.y);
    __nv_bfloat162 l = __floats2bfloat162_rn(rx, ry);
    hi = *reinterpret_cast<uint32_t*>(&h);
    lo = *reinterpret_cast<uint32_t*>(&l);
}

__device__ __forceinline__ void mma_bf16(float c[4], const uint32_t a[4], const uint32_t b[2]) {
    asm volatile(
        "mma.sync.aligned.m16n8k16.row.col.f32.bf16.bf16.f32 "
        "{%0,%1,%2,%3}, {%4,%5,%6,%7}, {%8,%9}, {%0,%1,%2,%3};\n"
        : "+f"(c[0]), "+f"(c[1]), "+f"(c[2]), "+f"(c[3])
        : "r"(a[0]), "r"(a[1]), "r"(a[2]), "r"(a[3]), "r"(b[0]), "r"(b[1]));
}

__device__ __forceinline__ uint32_t s2u(const void* p) {
    uint32_t a;
    asm("{ .reg .u64 t; cvta.to.shared.u64 t, %1; cvt.u32.u64 %0, t; }" : "=r"(a) : "l"(p));
    return a;
}

__device__ __forceinline__ void ldsm_x4(uint32_t r[4], uint32_t addr) {
    asm volatile("ldmatrix.sync.aligned.m8n8.x4.shared.b16 {%0,%1,%2,%3}, [%4];"
                 : "=r"(r[0]), "=r"(r[1]), "=r"(r[2]), "=r"(r[3]) : "r"(addr));
}

__device__ __forceinline__ void ldsm_x2(uint32_t r[2], uint32_t addr) {
    asm volatile("ldmatrix.sync.aligned.m8n8.x2.shared.b16 {%0,%1}, [%2];"
                 : "=r"(r[0]), "=r"(r[1]) : "r"(addr));
}

#define KM_STRIDE 20    // K-major row stride in words ([row][kword]), conflict-free for LDSM
#define BN_STRIDE 136   // NN B layout [kword][n] stride

// C[M,Nn] = scale * A[M,Kk] @ B, fp32 in/out, bf16x2 split (3-term) tensor-core math.
// BT=false: B is [Kk,Nn] row-major (NN). BT=true: B is [Nn,Kk] row-major (NT).
// Requires M%128==0, Nn%128==0, Kk%32==0.
template <bool BT>
__global__ void __launch_bounds__(256) gemm_bf16x2(
    const float* __restrict__ A, const float* __restrict__ B, float* __restrict__ C,
    int M, int Nn, int Kk, float scale)
{
    __shared__ uint32_t pool[10240];   // 40 KB
    uint32_t* const Ah = pool;                 // [128][20]
    uint32_t* const Al = pool + 2560;          // [128][20]
    // BT: B K-major [128][20] h/l ; NN: B [16][136] h/l
    uint32_t* const Bth = pool + 5120;
    uint32_t* const Btl = pool + 7680;
    uint32_t* const Bnh = pool + 5120;
    uint32_t* const Bnl = pool + 5120 + 2176;

    const int t = threadIdx.x;
    const int bRow = blockIdx.y * 128;
    const int bCol = blockIdx.x * 128;
    const int warp = t >> 5, lane = t & 31;
    const int wm = warp & 1;   // 2 warps along M -> 64-row warp tile
    const int wn = warp >> 1;  // 4 warps along N -> 32-col warp tile
    const int g = lane >> 2, tq = lane & 3;

    // Per-thread GMEM load coordinates (fixed across k-tiles)
    const int aRow = (t >> 3);          // +p*32
    const int aK   = (t & 7) * 4;       // 4 consecutive k
    const int bnRow = (t >> 3);         // BT: n base (+p*32)
    const int bnK   = (t & 7) * 4;
    const int bkRow = (t >> 5);         // NN: k base (+p*8)
    const int bNq   = (t & 31) * 4;     // 4 consecutive n

    // ldmatrix per-thread source addresses (byte SMEM addresses)
    const int aLrow = lane & 15;
    const int aLkw  = (lane >> 4) * 4;
    uint32_t aAddrH[4], aAddrL[4], bAddrH[4], bAddrL[4];
#pragma unroll
    for (int mt = 0; mt < 4; ++mt) {
        int r = wm * 64 + mt * 16 + aLrow;
        aAddrH[mt] = s2u(&Ah[r * KM_STRIDE + aLkw]);
        aAddrL[mt] = s2u(&Al[r * KM_STRIDE + aLkw]);
    }
    if (BT) {
        const int bLrow = lane & 7;
        const int bLkw  = ((lane >> 3) & 1) * 4;
#pragma unroll
        for (int nt = 0; nt < 4; ++nt) {
            int n = wn * 32 + nt * 8 + bLrow;
            bAddrH[nt] = s2u(&Bth[n * KM_STRIDE + bLkw]);
            bAddrL[nt] = s2u(&Btl[n * KM_STRIDE + bLkw]);
        }
    }

    float acc[4][4][4];
#pragma unroll
    for (int i = 0; i < 4; ++i)
#pragma unroll
        for (int j = 0; j < 4; ++j)
#pragma unroll
            for (int k = 0; k < 4; ++k) acc[i][j][k] = 0.f;

    float4 aReg[4], bReg[4];

    // ---- prefetch tile 0 ----
#pragma unroll
    for (int p = 0; p < 4; ++p)
        aReg[p] = *(const float4*)(A + (size_t)(bRow + aRow + p * 32) * Kk + aK);
    if (BT) {
#pragma unroll
        for (int p = 0; p < 4; ++p)
            bReg[p] = *(const float4*)(B + (size_t)(bCol + bnRow + p * 32) * Kk + bnK);
    } else {
#pragma unroll
        for (int p = 0; p < 4; ++p)
            bReg[p] = *(const float4*)(B + (size_t)(bkRow + p * 8) * Nn + bCol + bNq);
    }

    for (int kt = 0; kt < Kk; kt += 32) {
        // ---- split + store current tile regs -> SMEM ----
#pragma unroll
        for (int p = 0; p < 4; ++p) {
            int row = aRow + p * 32;
            uint32_t h0, l0, h1, l1;
            split_pack2(aReg[p].x, aReg[p].y, h0, l0);
            split_pack2(aReg[p].z, aReg[p].w, h1, l1);
            Ah[row * KM_STRIDE + (aK >> 1) + 0] = h0;  Al[row * KM_STRIDE + (aK >> 1) + 0] = l0;
            Ah[row * KM_STRIDE + (aK >> 1) + 1] = h1;  Al[row * KM_STRIDE + (aK >> 1) + 1] = l1;
        }
        if (BT) {
#pragma unroll
            for (int p = 0; p < 4; ++p) {
                int n = bnRow + p * 32;
                uint32_t h0, l0, h1, l1;
                split_pack2(bReg[p].x, bReg[p].y, h0, l0);
                split_pack2(bReg[p].z, bReg[p].w, h1, l1);
                Bth[n * KM_STRIDE + (bnK >> 1) + 0] = h0;  Btl[n * KM_STRIDE + (bnK >> 1) + 0] = l0;
                Bth[n * KM_STRIDE + (bnK >> 1) + 1] = h1;  Btl[n * KM_STRIDE + (bnK >> 1) + 1] = l1;
            }
        } else {
#pragma unroll
            for (int p = 0; p < 4; ++p) {
                int k = bkRow + p * 8;
                const float v[4] = {bReg[p].x, bReg[p].y, bReg[p].z, bReg[p].w};
#pragma unroll
                for (int j = 0; j < 4; ++j) {
                    int n = bNq + j;
                    __nv_bfloat16 h = __float2bfloat16_rn(v[j]);
                    __nv_bfloat16 l = __float2bfloat16_rn(v[j] - __bfloat162float(h));
                    ((__nv_bfloat16*)&Bnh[(k >> 1) * BN_STRIDE + n])[k & 1] = h;
                    ((__nv_bfloat16*)&Bnl[(k >> 1) * BN_STRIDE + n])[k & 1] = l;
                }
            }
        }
        __syncthreads();

        // ---- prefetch next tile (overlapped by MMAs below) ----
        const int kn = kt + 32;
        if (kn < Kk) {
#pragma unroll
            for (int p = 0; p < 4; ++p)
                aReg[p] = *(const float4*)(A + (size_t)(bRow + aRow + p * 32) * Kk + kn + aK);
            if (BT) {
#pragma unroll
                for (int p = 0; p < 4; ++p)
                    bReg[p] = *(const float4*)(B + (size_t)(bCol + bnRow + p * 32) * Kk + kn + bnK);
            } else {
#pragma unroll
                for (int p = 0; p < 4; ++p)
                    bReg[p] = *(const float4*)(B + (size_t)(kn + bkRow + p * 8) * Nn + bCol + bNq);
            }
        }

        // ---- MMA: two k16 steps per 32-k tile, 3-term split product ----
#pragma unroll
        for (int ks2 = 0; ks2 < 16; ks2 += 8) {   // kword base: 0, 8
            uint32_t ah[4][4], al[4][4], bh[4][2], bl[4][2];
#pragma unroll
            for (int mt = 0; mt < 4; ++mt) {
                ldsm_x4(ah[mt], aAddrH[mt] + ks2 * 4);
                ldsm_x4(al[mt], aAddrL[mt] + ks2 * 4);
            }
            if (BT) {
#pragma unroll
                for (int nt = 0; nt < 4; ++nt) {
                    ldsm_x2(bh[nt], bAddrH[nt] + ks2 * 4);
                    ldsm_x2(bl[nt], bAddrL[nt] + ks2 * 4);
                }
            } else {
#pragma unroll
                for (int nt = 0; nt < 4; ++nt) {
                    int c = wn * 32 + nt * 8 + g;
                    int w = ks2 + tq;
                    bh[nt][0] = Bnh[w * BN_STRIDE + c]; bh[nt][1] = Bnh[(w + 4) * BN_STRIDE + c];
                    bl[nt][0] = Bnl[w * BN_STRIDE + c]; bl[nt][1] = Bnl[(w + 4) * BN_STRIDE + c];
                }
            }
#pragma unroll
            for (int mt = 0; mt < 4; ++mt)
#pragma unroll
                for (int nt = 0; nt < 4; ++nt) {
                    mma_bf16(acc[mt][nt], ah[mt], bh[nt]);
                    mma_bf16(acc[mt][nt], ah[mt], bl[nt]);
                    mma_bf16(acc[mt][nt], al[mt], bh[nt]);
                }
        }
        __syncthreads();
    }

    // ---- epilogue ----
#pragma unroll
    for (int mt = 0; mt < 4; ++mt) {
#pragma unroll
        for (int nt = 0; nt < 4; ++nt) {
            int r = bRow + wm * 64 + mt * 16 + g;
            int c = bCol + wn * 32 + nt * 8 + tq * 2;
            float2 v0 = make_float2(acc[mt][nt][0] * scale, acc[mt][nt][1] * scale);
            float2 v1 = make_float2(acc[mt][nt][2] * scale, acc[mt][nt][3] * scale);
            *(float2*)(C + (size_t)r * Nn + c) = v0;
            *(float2*)(C + (size_t)(r + 8) * Nn + c) = v1;
        }
    }
}

// In-place row softmax over S[NTOK][NTOK]. One block per row.
__global__ void __launch_bounds__(256) softmax_rows(float* __restrict__ S) {
    __shared__ float buf[NTOK];   // 32 KB: full row
    __shared__ float red[8];
    const int row = blockIdx.x;
    const int t = threadIdx.x;
    float* rp = S + (size_t)row * NTOK;

    float lmax = -INFINITY;
#pragma unroll
    for (int i = 0; i < 8; ++i) {
        int idx = (i * 256 + t) * 4;
        float4 v = *(const float4*)(rp + idx);
        *(float4*)(buf + idx) = v;
        lmax = fmaxf(lmax, fmaxf(fmaxf(v.x, v.y), fmaxf(v.z, v.w)));
    }
#pragma unroll
    for (int o = 16; o; o >>= 1) lmax = fmaxf(lmax, __shfl_xor_sync(0xffffffffu, lmax, o));
    if ((t & 31) == 0) red[t >> 5] = lmax;
    __syncthreads();
    float m = red[0];
#pragma unroll
    for (int i = 1; i < 8; ++i) m = fmaxf(m, red[i]);
    __syncthreads();

    float lsum = 0.f;
#pragma unroll
    for (int i = 0; i < 8; ++i) {
        int idx = (i * 256 + t) * 4;
        float4 v = *(const float4*)(buf + idx);
        v.x = __expf(v.x - m);
        v.y = __expf(v.y - m);
        v.z = __expf(v.z - m);
        v.w = __expf(v.w - m);
        lsum += (v.x + v.y) + (v.z + v.w);
        *(float4*)(buf + idx) = v;
    }
#pragma unroll
    for (int o = 16; o; o >>= 1) lsum += __shfl_xor_sync(0xffffffffu, lsum, o);
    if ((t & 31) == 0) red[t >> 5] = lsum;
    __syncthreads();
    float s = red[0];
#pragma unroll
    for (int i = 1; i < 8; ++i) s += red[i];
    float inv = 1.f / s;

#pragma unroll
    for (int i = 0; i < 8; ++i) {
        int idx = (i * 256 + t) * 4;
        float4 v = *(const float4*)(buf + idx);
        v.x *= inv; v.y *= inv; v.z *= inv; v.w *= inv;
        *(float4*)(rp + idx) = v;
    }
}

extern "C" void kernel_launch(void* const* d_in, const int* in_sizes, int n_in,
                              void* d_out, int out_size)
{
    const float* x  = (const float*)d_in[0];
    const float* wq = (const float*)d_in[1];
    const float* wk = (const float*)d_in[2];
    const float* wv = (const float*)d_in[3];
    float* out = (float*)d_out;

    static float *Q = nullptr, *K = nullptr, *V = nullptr, *S = nullptr;
    if (!Q) {
        cudaGetSymbolAddress((void**)&Q, g_Q);
        cudaGetSymbolAddress((void**)&K, g_K);
        cudaGetSymbolAddress((void**)&V, g_V);
        cudaGetSymbolAddress((void**)&S, g_S);
    }

    // Projections: [8192,1024] @ [1024,1024]  (NN)
    dim3 gProj(DDIM / 128, NTOK / 128);
    gemm_bf16x2<false><<<gProj, 256>>>(x, wq, Q, NTOK, DDIM, DDIM, 1.f);
    gemm_bf16x2<false><<<gProj, 256>>>(x, wk, K, NTOK, DDIM, DDIM, 1.f);
    gemm_bf16x2<false><<<gProj, 256>>>(x, wv, V, NTOK, DDIM, DDIM, 1.f);

    // Scores: Q @ K^T * (1/sqrt(1024))  (NT)
    dim3 gScore(NTOK / 128, NTOK / 128);
    gemm_bf16x2<true><<<gScore, 256>>>(Q, K, S, NTOK, NTOK, DDIM, 0.03125f);

    // Row softmax in place
    softmax_rows<<<NTOK, 256>>>(S);

    // Output: P @ V  (NN)
    dim3 gOut(DDIM / 128, NTOK / 128);
    gemm_bf16x2<false><<<gOut, 256>>>(S, V, out, NTOK, DDIM, NTOK, 1.f);
}

// round 7
// speedup vs baseline: 1.2011x; 1.1488x over previous
#include <cuda_runtime.h>
#include <cuda_bf16.h>
#include <cstdint>
#include <cmath>

#define NTOK 8192
#define DDIM 1024

typedef __nv_bfloat16 bf16;

// ---------------- scratch (allocation-free rule: __device__ globals) ----------------
__device__ float g_S [(size_t)NTOK * NTOK];
__device__ float g_Vf[(size_t)NTOK * DDIM];
__device__ bf16  g_xh[(size_t)NTOK * DDIM], g_xl[(size_t)NTOK * DDIM];
__device__ bf16  g_wqh[DDIM * DDIM], g_wql[DDIM * DDIM];   // transposed [n][k]
__device__ bf16  g_wkh[DDIM * DDIM], g_wkl[DDIM * DDIM];
__device__ bf16  g_wvh[DDIM * DDIM], g_wvl[DDIM * DDIM];
__device__ bf16  g_Qh[(size_t)NTOK * DDIM], g_Ql[(size_t)NTOK * DDIM];
__device__ bf16  g_Kh[(size_t)NTOK * DDIM], g_Kl[(size_t)NTOK * DDIM];
__device__ bf16  g_Vth[(size_t)DDIM * NTOK], g_Vtl[(size_t)DDIM * NTOK]; // [n][k]
__device__ bf16  g_Ph[(size_t)NTOK * NTOK], g_Pl[(size_t)NTOK * NTOK];

// ---------------- helpers ----------------
__device__ __forceinline__ uint32_t s2u(const void* p) {
    uint32_t a;
    asm("{ .reg .u64 t; cvta.to.shared.u64 t, %1; cvt.u32.u64 %0, t; }" : "=r"(a) : "l"(p));
    return a;
}
__device__ __forceinline__ void cp16(uint32_t dst, const void* src) {
    asm volatile("cp.async.cg.shared.global [%0], [%1], 16;" :: "r"(dst), "l"(src) : "memory");
}
__device__ __forceinline__ void cp_commit() { asm volatile("cp.async.commit_group;" ::: "memory"); }
template <int N>
__device__ __forceinline__ void cp_wait() { asm volatile("cp.async.wait_group %0;" :: "n"(N) : "memory"); }

__device__ __forceinline__ void mma_bf16(float c[4], const uint32_t a[4], const uint32_t b[2]) {
    asm volatile(
        "mma.sync.aligned.m16n8k16.row.col.f32.bf16.bf16.f32 "
        "{%0,%1,%2,%3}, {%4,%5,%6,%7}, {%8,%9}, {%0,%1,%2,%3};\n"
        : "+f"(c[0]), "+f"(c[1]), "+f"(c[2]), "+f"(c[3])
        : "r"(a[0]), "r"(a[1]), "r"(a[2]), "r"(a[3]), "r"(b[0]), "r"(b[1]));
}
__device__ __forceinline__ void ldsm_x4(uint32_t r[4], uint32_t addr) {
    asm volatile("ldmatrix.sync.aligned.m8n8.x4.shared.b16 {%0,%1,%2,%3}, [%4];"
                 : "=r"(r[0]), "=r"(r[1]), "=r"(r[2]), "=r"(r[3]) : "r"(addr));
}
__device__ __forceinline__ void ldsm_x2(uint32_t r[2], uint32_t addr) {
    asm volatile("ldmatrix.sync.aligned.m8n8.x2.shared.b16 {%0,%1}, [%2];"
                 : "=r"(r[0]), "=r"(r[1]) : "r"(addr));
}

// SMEM stage layout: 4 arrays (Ah, Al, Bh, Bl), each [128 rows][20 words] (16 payload + 4 pad).
// Stride 20 words = 80B: 16B-granule index 5r mod 8 is bijective -> LDSM conflict-free.
#define KM_STRIDE   20
#define ARR_WORDS   (128 * KM_STRIDE)          // 2560
#define STAGE_WORDS (4 * ARR_WORDS)            // 10240
#define STAGE_BYTES (STAGE_WORDS * 4)          // 40960
#define DSM_BYTES   (2 * STAGE_BYTES)          // 81920

// C[M][Nn] = scale * (Ah+Al)[M][Kk] @ (Bh+Bl)[Nn][Kk]^T   (3-term split product)
// EPI=0: Cf fp32 out; EPI=1: Ch/Cl split-bf16 out. grid = (Nn/128, M/128), 256 threads.
template <int EPI>
__global__ void __launch_bounds__(256, 1)
gemm_nt(const bf16* __restrict__ Ah, const bf16* __restrict__ Al,
        const bf16* __restrict__ Bh, const bf16* __restrict__ Bl,
        float* __restrict__ Cf, bf16* __restrict__ Ch, bf16* __restrict__ Cl,
        int Nn, int Kk, float scale)
{
    extern __shared__ uint32_t smem[];
    const uint32_t sbase = s2u(smem);

    const int t = threadIdx.x;
    const int warp = t >> 5, lane = t & 31;
    const int bRow = blockIdx.y * 128, bCol = blockIdx.x * 128;
    const int wm = warp & 1;   // 2 warps along M -> 64-row warp tile
    const int wn = warp >> 1;  // 4 warps along N -> 32-col warp tile
    const int g = lane >> 2, tq = lane & 3;

    // cp.async assignment: 2048 16B-chunks/stage, 8 per thread.
    // j = 0..7: array a = j>>1, row = (j&1)*64 + t/4, chunk c = t&3.
    const bf16* gsrc[4] = {
        Ah + (size_t)bRow * Kk, Al + (size_t)bRow * Kk,
        Bh + (size_t)bCol * Kk, Bl + (size_t)bCol * Kk };
    const int cpRow = t >> 2, cpC = t & 3;

    // ldmatrix per-thread base addresses (byte SMEM offsets within a stage)
    const int aLrow = lane & 15;
    const int aLkw  = (lane >> 4) * 4;
    const int bLrow = lane & 7;
    const int bLkw  = ((lane >> 3) & 1) * 4;
    uint32_t aOffH[4], bOffH[4];
#pragma unroll
    for (int mt = 0; mt < 4; ++mt)
        aOffH[mt] = (uint32_t)(((wm * 64 + mt * 16 + aLrow) * KM_STRIDE + aLkw) * 4);
#pragma unroll
    for (int nt = 0; nt < 4; ++nt)
        bOffH[nt] = (uint32_t)((2 * ARR_WORDS + (wn * 32 + nt * 8 + bLrow) * KM_STRIDE + bLkw) * 4);
    const uint32_t loDelta = ARR_WORDS * 4;   // h -> l array offset (bytes)

    float acc[4][4][4];
#pragma unroll
    for (int i = 0; i < 4; ++i)
#pragma unroll
        for (int j = 0; j < 4; ++j)
#pragma unroll
            for (int k = 0; k < 4; ++k) acc[i][j][k] = 0.f;

    const int KT = Kk >> 5;   // 32-elem k-tiles

    // ---- copy stage helper (issued by all threads) ----
    auto copy_stage = [&](int s, int it) {
        const uint32_t sb = sbase + s * STAGE_BYTES;
        const int kOff = it * 32;
#pragma unroll
        for (int j = 0; j < 8; ++j) {
            const int a = j >> 1;
            const int r = (j & 1) * 64 + cpRow;
            const bf16* src = gsrc[a] + (size_t)r * Kk + kOff + cpC * 8;
            uint32_t dst = sb + (uint32_t)((a * ARR_WORDS + r * KM_STRIDE + cpC * 4) * 4);
            cp16(dst, src);
        }
        cp_commit();
    };

    copy_stage(0, 0);

    for (int it = 0; it < KT; ++it) {
        const int s = it & 1;
        if (it + 1 < KT) { copy_stage(s ^ 1, it + 1); cp_wait<1>(); }
        else             { cp_wait<0>(); }
        __syncthreads();

        const uint32_t sb = sbase + s * STAGE_BYTES;
#pragma unroll
        for (int ks2 = 0; ks2 < 16; ks2 += 8) {     // two k16 steps
            uint32_t ah[4][4], al[4][4], bh[4][2], bl[4][2];
#pragma unroll
            for (int mt = 0; mt < 4; ++mt) {
                uint32_t ad = sb + aOffH[mt] + ks2 * 4;
                ldsm_x4(ah[mt], ad);
                ldsm_x4(al[mt], ad + loDelta);
            }
#pragma unroll
            for (int nt = 0; nt < 4; ++nt) {
                uint32_t bd = sb + bOffH[nt] + ks2 * 4;
                ldsm_x2(bh[nt], bd);
                ldsm_x2(bl[nt], bd + loDelta);
            }
#pragma unroll
            for (int mt = 0; mt < 4; ++mt)
#pragma unroll
                for (int nt = 0; nt < 4; ++nt) {
                    mma_bf16(acc[mt][nt], ah[mt], bh[nt]);
                    mma_bf16(acc[mt][nt], ah[mt], bl[nt]);
                    mma_bf16(acc[mt][nt], al[mt], bh[nt]);
                }
        }
        __syncthreads();
    }

    // ---- epilogue: direct stores from accumulators ----
#pragma unroll
    for (int mt = 0; mt < 4; ++mt) {
#pragma unroll
        for (int nt = 0; nt < 4; ++nt) {
            int r = bRow + wm * 64 + mt * 16 + g;
            int c = bCol + wn * 32 + nt * 8 + tq * 2;
            float v0 = acc[mt][nt][0] * scale, v1 = acc[mt][nt][1] * scale;
            float v2 = acc[mt][nt][2] * scale, v3 = acc[mt][nt][3] * scale;
            if (EPI == 0) {
                *(float2*)(Cf + (size_t)r * Nn + c) = make_float2(v0, v1);
                *(float2*)(Cf + (size_t)(r + 8) * Nn + c) = make_float2(v2, v3);
            } else {
                bf16 h0 = __float2bfloat16_rn(v0), h1 = __float2bfloat16_rn(v1);
                bf16 h2 = __float2bfloat16_rn(v2), h3 = __float2bfloat16_rn(v3);
                __nv_bfloat162 hp0; hp0.x = h0; hp0.y = h1;
                __nv_bfloat162 hp1; hp1.x = h2; hp1.y = h3;
                __nv_bfloat162 lp0, lp1;
                lp0.x = __float2bfloat16_rn(v0 - __bfloat162float(h0));
                lp0.y = __float2bfloat16_rn(v1 - __bfloat162float(h1));
                lp1.x = __float2bfloat16_rn(v2 - __bfloat162float(h2));
                lp1.y = __float2bfloat16_rn(v3 - __bfloat162float(h3));
                *(__nv_bfloat162*)(Ch + (size_t)r * Nn + c) = hp0;
                *(__nv_bfloat162*)(Ch + (size_t)(r + 8) * Nn + c) = hp1;
                *(__nv_bfloat162*)(Cl + (size_t)r * Nn + c) = lp0;
                *(__nv_bfloat162*)(Cl + (size_t)(r + 8) * Nn + c) = lp1;
            }
        }
    }
}

// ---------------- prep kernels ----------------
__global__ void split_pair(const float* __restrict__ src, bf16* __restrict__ h,
                           bf16* __restrict__ l, size_t n)
{
    size_t stride = (size_t)gridDim.x * blockDim.x * 4;
    for (size_t i = ((size_t)blockIdx.x * blockDim.x + threadIdx.x) * 4; i < n; i += stride) {
        float4 v = *(const float4*)(src + i);
        bf16 h0 = __float2bfloat16_rn(v.x), h1 = __float2bfloat16_rn(v.y);
        bf16 h2 = __float2bfloat16_rn(v.z), h3 = __float2bfloat16_rn(v.w);
        h[i + 0] = h0; h[i + 1] = h1; h[i + 2] = h2; h[i + 3] = h3;
        l[i + 0] = __float2bfloat16_rn(v.x - __bfloat162float(h0));
        l[i + 1] = __float2bfloat16_rn(v.y - __bfloat162float(h1));
        l[i + 2] = __float2bfloat16_rn(v.z - __bfloat162float(h2));
        l[i + 3] = __float2bfloat16_rn(v.w - __bfloat162float(h3));
    }
}

// transpose + split: src[R][C] fp32 -> th/tl[C][R] bf16
__global__ void tsplit(const float* __restrict__ src, bf16* __restrict__ th,
                       bf16* __restrict__ tl, int R, int C)
{
    __shared__ float buf[32][33];
    const int bx = blockIdx.x * 32;   // C offset
    const int by = blockIdx.y * 32;   // R offset
    const int t = threadIdx.x;
#pragma unroll
    for (int j = 0; j < 4; ++j) {
        int idx = t + 256 * j; int r = idx >> 5, c = idx & 31;
        buf[r][c] = src[(size_t)(by + r) * C + bx + c];
    }
    __syncthreads();
#pragma unroll
    for (int j = 0; j < 4; ++j) {
        int idx = t + 256 * j; int c = idx >> 5, r = idx & 31;
        float v = buf[r][c];
        size_t o = (size_t)(bx + c) * R + by + r;
        bf16 h = __float2bfloat16_rn(v);
        th[o] = h;
        tl[o] = __float2bfloat16_rn(v - __bfloat162float(h));
    }
}

// row softmax over S fp32, emit P as bf16 hi/lo pair. One block per row.
__global__ void __launch_bounds__(256) softmax_split(const float* __restrict__ S,
                                                     bf16* __restrict__ Ph,
                                                     bf16* __restrict__ Pl)
{
    __shared__ float buf[NTOK];
    __shared__ float red[8];
    const int row = blockIdx.x, t = threadIdx.x;
    const float* rp = S + (size_t)row * NTOK;

    float lmax = -INFINITY;
#pragma unroll
    for (int i = 0; i < 8; ++i) {
        int idx = (i * 256 + t) * 4;
        float4 v = *(const float4*)(rp + idx);
        *(float4*)(buf + idx) = v;
        lmax = fmaxf(lmax, fmaxf(fmaxf(v.x, v.y), fmaxf(v.z, v.w)));
    }
#pragma unroll
    for (int o = 16; o; o >>= 1) lmax = fmaxf(lmax, __shfl_xor_sync(0xffffffffu, lmax, o));
    if ((t & 31) == 0) red[t >> 5] = lmax;
    __syncthreads();
    float m = red[0];
#pragma unroll
    for (int i = 1; i < 8; ++i) m = fmaxf(m, red[i]);
    __syncthreads();

    float lsum = 0.f;
#pragma unroll
    for (int i = 0; i < 8; ++i) {
        int idx = (i * 256 + t) * 4;
        float4 v = *(const float4*)(buf + idx);
        v.x = __expf(v.x - m); v.y = __expf(v.y - m);
        v.z = __expf(v.z - m); v.w = __expf(v.w - m);
        lsum += (v.x + v.y) + (v.z + v.w);
        *(float4*)(buf + idx) = v;
    }
#pragma unroll
    for (int o = 16; o; o >>= 1) lsum += __shfl_xor_sync(0xffffffffu, lsum, o);
    if ((t & 31) == 0) red[t >> 5] = lsum;
    __syncthreads();
    float s = red[0];
#pragma unroll
    for (int i = 1; i < 8; ++i) s += red[i];
    const float inv = 1.f / s;

    bf16* ph = Ph + (size_t)row * NTOK;
    bf16* pl = Pl + (size_t)row * NTOK;
#pragma unroll
    for (int i = 0; i < 8; ++i) {
        int idx = (i * 256 + t) * 4;
        float4 v = *(const float4*)(buf + idx);
        float p0 = v.x * inv, p1 = v.y * inv, p2 = v.z * inv, p3 = v.w * inv;
        bf16 h0 = __float2bfloat16_rn(p0), h1 = __float2bfloat16_rn(p1);
        bf16 h2 = __float2bfloat16_rn(p2), h3 = __float2bfloat16_rn(p3);
        ph[idx] = h0; ph[idx + 1] = h1; ph[idx + 2] = h2; ph[idx + 3] = h3;
        pl[idx]     = __float2bfloat16_rn(p0 - __bfloat162float(h0));
        pl[idx + 1] = __float2bfloat16_rn(p1 - __bfloat162float(h1));
        pl[idx + 2] = __float2bfloat16_rn(p2 - __bfloat162float(h2));
        pl[idx + 3] = __float2bfloat16_rn(p3 - __bfloat162float(h3));
    }
}

// ---------------- launcher ----------------
extern "C" void kernel_launch(void* const* d_in, const int* in_sizes, int n_in,
                              void* d_out, int out_size)
{
    const float* x  = (const float*)d_in[0];
    const float* wq = (const float*)d_in[1];
    const float* wk = (const float*)d_in[2];
    const float* wv = (const float*)d_in[3];
    float* out = (float*)d_out;

    static bool inited = false;
    static float *S, *Vf;
    static bf16 *xh, *xl, *wqh, *wql, *wkh, *wkl, *wvh, *wvl;
    static bf16 *Qh, *Ql, *Kh, *Kl, *Vth, *Vtl, *Ph, *Pl;
    if (!inited) {
        inited = true;
        cudaFuncSetAttribute(gemm_nt<0>, cudaFuncAttributeMaxDynamicSharedMemorySize, DSM_BYTES);
        cudaFuncSetAttribute(gemm_nt<1>, cudaFuncAttributeMaxDynamicSharedMemorySize, DSM_BYTES);
        cudaGetSymbolAddress((void**)&S,   g_S);
        cudaGetSymbolAddress((void**)&Vf,  g_Vf);
        cudaGetSymbolAddress((void**)&xh,  g_xh);  cudaGetSymbolAddress((void**)&xl,  g_xl);
        cudaGetSymbolAddress((void**)&wqh, g_wqh); cudaGetSymbolAddress((void**)&wql, g_wql);
        cudaGetSymbolAddress((void**)&wkh, g_wkh); cudaGetSymbolAddress((void**)&wkl, g_wkl);
        cudaGetSymbolAddress((void**)&wvh, g_wvh); cudaGetSymbolAddress((void**)&wvl, g_wvl);
        cudaGetSymbolAddress((void**)&Qh,  g_Qh);  cudaGetSymbolAddress((void**)&Ql,  g_Ql);
        cudaGetSymbolAddress((void**)&Kh,  g_Kh);  cudaGetSymbolAddress((void**)&Kl,  g_Kl);
        cudaGetSymbolAddress((void**)&Vth, g_Vth); cudaGetSymbolAddress((void**)&Vtl, g_Vtl);
        cudaGetSymbolAddress((void**)&Ph,  g_Ph);  cudaGetSymbolAddress((void**)&Pl,  g_Pl);
    }

    // prep: split x; transpose+split weights
    split_pair<<<2048, 256>>>(x, xh, xl, (size_t)NTOK * DDIM);
    dim3 gW(DDIM / 32, DDIM / 32);
    tsplit<<<gW, 256>>>(wq, wqh, wql, DDIM, DDIM);
    tsplit<<<gW, 256>>>(wk, wkh, wkl, DDIM, DDIM);
    tsplit<<<gW, 256>>>(wv, wvh, wvl, DDIM, DDIM);

    // projections (NT vs transposed weights): [8192,1024] x [1024,1024]
    dim3 gProj(DDIM / 128, NTOK / 128);
    gemm_nt<1><<<gProj, 256, DSM_BYTES>>>(xh, xl, wqh, wql, nullptr, Qh, Ql, DDIM, DDIM, 1.f);
    gemm_nt<1><<<gProj, 256, DSM_BYTES>>>(xh, xl, wkh, wkl, nullptr, Kh, Kl, DDIM, DDIM, 1.f);
    gemm_nt<0><<<gProj, 256, DSM_BYTES>>>(xh, xl, wvh, wvl, Vf, nullptr, nullptr, DDIM, DDIM, 1.f);

    // V^T split for PV
    dim3 gV(DDIM / 32, NTOK / 32);
    tsplit<<<gV, 256>>>(Vf, Vth, Vtl, NTOK, DDIM);

    // scores: S = Q K^T / 32
    dim3 gS(NTOK / 128, NTOK / 128);
    gemm_nt<0><<<gS, 256, DSM_BYTES>>>(Qh, Ql, Kh, Kl, S, nullptr, nullptr, NTOK, DDIM, 0.03125f);

    // softmax -> split P
    softmax_split<<<NTOK, 256>>>(S, Ph, Pl);

    // out = P V
    dim3 gO(DDIM / 128, NTOK / 128);
    gemm_nt<0><<<gO, 256, DSM_BYTES>>>(Ph, Pl, Vth, Vtl, out, nullptr, nullptr, DDIM, NTOK, 1.f);
}

// round 9
// speedup vs baseline: 1.2532x; 1.0434x over previous
#include <cuda_runtime.h>
#include <cuda_bf16.h>
#include <cstdint>
#include <cmath>

#define NTOK 8192
#define DDIM 1024

typedef __nv_bfloat16 bf16;

// ---------------- scratch (allocation-free rule: __device__ globals) ----------------
__device__ float g_S [(size_t)NTOK * NTOK];
__device__ float g_Vf[(size_t)NTOK * DDIM];
__device__ bf16  g_xh[(size_t)NTOK * DDIM], g_xl[(size_t)NTOK * DDIM];
__device__ bf16  g_wqh[DDIM * DDIM], g_wql[DDIM * DDIM];   // transposed [n][k]
__device__ bf16  g_wkh[DDIM * DDIM], g_wkl[DDIM * DDIM];
__device__ bf16  g_wvh[DDIM * DDIM], g_wvl[DDIM * DDIM];
__device__ bf16  g_Qh[(size_t)NTOK * DDIM], g_Ql[(size_t)NTOK * DDIM];
__device__ bf16  g_Kh[(size_t)NTOK * DDIM], g_Kl[(size_t)NTOK * DDIM];
__device__ bf16  g_Vth[(size_t)DDIM * NTOK], g_Vtl[(size_t)DDIM * NTOK]; // [n][k]
__device__ bf16  g_Ph[(size_t)NTOK * NTOK], g_Pl[(size_t)NTOK * NTOK];

// ---------------- helpers ----------------
__device__ __forceinline__ uint32_t s2u(const void* p) {
    uint32_t a;
    asm("{ .reg .u64 t; cvta.to.shared.u64 t, %1; cvt.u32.u64 %0, t; }" : "=r"(a) : "l"(p));
    return a;
}
__device__ __forceinline__ void cp16(uint32_t dst, const void* src) {
    asm volatile("cp.async.cg.shared.global [%0], [%1], 16;" :: "r"(dst), "l"(src) : "memory");
}
__device__ __forceinline__ void cp_commit() { asm volatile("cp.async.commit_group;" ::: "memory"); }
template <int N>
__device__ __forceinline__ void cp_wait() { asm volatile("cp.async.wait_group %0;" :: "n"(N) : "memory"); }

__device__ __forceinline__ void mma_bf16(float c[4], const uint32_t a[4], const uint32_t b[2]) {
    asm volatile(
        "mma.sync.aligned.m16n8k16.row.col.f32.bf16.bf16.f32 "
        "{%0,%1,%2,%3}, {%4,%5,%6,%7}, {%8,%9}, {%0,%1,%2,%3};\n"
        : "+f"(c[0]), "+f"(c[1]), "+f"(c[2]), "+f"(c[3])
        : "r"(a[0]), "r"(a[1]), "r"(a[2]), "r"(a[3]), "r"(b[0]), "r"(b[1]));
}
__device__ __forceinline__ void ldsm_x4(uint32_t r[4], uint32_t addr) {
    asm volatile("ldmatrix.sync.aligned.m8n8.x4.shared.b16 {%0,%1,%2,%3}, [%4];"
                 : "=r"(r[0]), "=r"(r[1]), "=r"(r[2]), "=r"(r[3]) : "r"(addr));
}
__device__ __forceinline__ void ldsm_x2(uint32_t r[2], uint32_t addr) {
    asm volatile("ldmatrix.sync.aligned.m8n8.x2.shared.b16 {%0,%1}, [%2];"
                 : "=r"(r[0]), "=r"(r[1]) : "r"(addr));
}

// SMEM stage layout: 4 arrays (Ah, Al, Bh, Bl), each [128 rows][20 words] (16 payload + 4 pad).
// Stride 20 words = 80B: 16B-granule index 5r mod 8 is bijective -> LDSM conflict-free.
#define KM_STRIDE   20
#define ARR_WORDS   (128 * KM_STRIDE)          // 2560
#define STAGE_WORDS (4 * ARR_WORDS)            // 10240
#define STAGE_BYTES (STAGE_WORDS * 4)          // 40960
#define NSTAGE      3
#define DSM_BYTES   (NSTAGE * STAGE_BYTES)     // 122880

// C[M][Nn] = scale * (Ah+Al)[M][Kk] @ (Bh+Bl)[Nn][Kk]^T   (3-term split product)
// EPI=0: Cf fp32 out; EPI=1: Ch/Cl split-bf16 out. grid = (Nn/128, M/128), 256 threads.
// Requires Kk/32 >= 2 (always true here).
template <int EPI>
__global__ void __launch_bounds__(256, 1)
gemm_nt(const bf16* __restrict__ Ah, const bf16* __restrict__ Al,
        const bf16* __restrict__ Bh, const bf16* __restrict__ Bl,
        float* __restrict__ Cf, bf16* __restrict__ Ch, bf16* __restrict__ Cl,
        int Nn, int Kk, float scale)
{
    extern __shared__ uint32_t smem[];
    const uint32_t sbase = s2u(smem);

    const int t = threadIdx.x;
    const int warp = t >> 5, lane = t & 31;
    const int bRow = blockIdx.y * 128, bCol = blockIdx.x * 128;
    const int wm = warp & 1;   // 2 warps along M -> 64-row warp tile
    const int wn = warp >> 1;  // 4 warps along N -> 32-col warp tile
    const int g = lane >> 2, tq = lane & 3;

    // cp.async assignment: 2048 16B-chunks/stage, 8 per thread.
    const bf16* gsrc[4] = {
        Ah + (size_t)bRow * Kk, Al + (size_t)bRow * Kk,
        Bh + (size_t)bCol * Kk, Bl + (size_t)bCol * Kk };
    const int cpRow = t >> 2, cpC = t & 3;

    // ldmatrix per-thread base addresses (byte SMEM offsets within a stage)
    const int aLrow = lane & 15;
    const int aLkw  = (lane >> 4) * 4;
    const int bLrow = lane & 7;
    const int bLkw  = ((lane >> 3) & 1) * 4;
    uint32_t aOffH[4], bOffH[4];
#pragma unroll
    for (int mt = 0; mt < 4; ++mt)
        aOffH[mt] = (uint32_t)(((wm * 64 + mt * 16 + aLrow) * KM_STRIDE + aLkw) * 4);
#pragma unroll
    for (int nt = 0; nt < 4; ++nt)
        bOffH[nt] = (uint32_t)((2 * ARR_WORDS + (wn * 32 + nt * 8 + bLrow) * KM_STRIDE + bLkw) * 4);
    const uint32_t loDelta = ARR_WORDS * 4;   // h -> l array offset (bytes)

    float acc[4][4][4];
#pragma unroll
    for (int i = 0; i < 4; ++i)
#pragma unroll
        for (int j = 0; j < 4; ++j)
#pragma unroll
            for (int k = 0; k < 4; ++k) acc[i][j][k] = 0.f;

    const int KT = Kk >> 5;   // 32-elem k-tiles

    auto copy_stage = [&](int s, int it) {
        const uint32_t sb = sbase + s * STAGE_BYTES;
        const int kOff = it * 32;
#pragma unroll
        for (int j = 0; j < 8; ++j) {
            const int a = j >> 1;
            const int r = (j & 1) * 64 + cpRow;
            const bf16* src = gsrc[a] + (size_t)r * Kk + kOff + cpC * 8;
            uint32_t dst = sb + (uint32_t)((a * ARR_WORDS + r * KM_STRIDE + cpC * 4) * 4);
            cp16(dst, src);
        }
    };

    // Prologue: tiles 0 and 1 in flight (one commit group each).
    copy_stage(0, 0); cp_commit();
    copy_stage(1, 1); cp_commit();

    int stage = 0;
    for (int it = 0; it < KT; ++it) {
        cp_wait<1>();          // group for tile `it` complete (invariant: 2 groups out)
        __syncthreads();       // all warps done reading stage from iter it-1 + data visible

        // Refill: tile it+2 into the stage read at iter it-1 (safe after the sync).
        if (it + 2 < KT) {
            int ns = stage + 2; if (ns >= NSTAGE) ns -= NSTAGE;
            copy_stage(ns, it + 2);
        }
        cp_commit();           // dummy at tail keeps wait<1> semantics exact

        const uint32_t sb = sbase + stage * STAGE_BYTES;
#pragma unroll
        for (int ks2 = 0; ks2 < 16; ks2 += 8) {     // two k16 steps
            uint32_t ah[4][4], al[4][4], bh[4][2], bl[4][2];
#pragma unroll
            for (int mt = 0; mt < 4; ++mt) {
                uint32_t ad = sb + aOffH[mt] + ks2 * 4;
                ldsm_x4(ah[mt], ad);
                ldsm_x4(al[mt], ad + loDelta);
            }
#pragma unroll
            for (int nt = 0; nt < 4; ++nt) {
                uint32_t bd = sb + bOffH[nt] + ks2 * 4;
                ldsm_x2(bh[nt], bd);
                ldsm_x2(bl[nt], bd + loDelta);
            }
#pragma unroll
            for (int mt = 0; mt < 4; ++mt)
#pragma unroll
                for (int nt = 0; nt < 4; ++nt) {
                    mma_bf16(acc[mt][nt], ah[mt], bh[nt]);
                    mma_bf16(acc[mt][nt], ah[mt], bl[nt]);
                    mma_bf16(acc[mt][nt], al[mt], bh[nt]);
                }
        }
        if (++stage == NSTAGE) stage = 0;
    }

    // ---- epilogue: direct stores from accumulators ----
#pragma unroll
    for (int mt = 0; mt < 4; ++mt) {
#pragma unroll
        for (int nt = 0; nt < 4; ++nt) {
            int r = bRow + wm * 64 + mt * 16 + g;
            int c = bCol + wn * 32 + nt * 8 + tq * 2;
            float v0 = acc[mt][nt][0] * scale, v1 = acc[mt][nt][1] * scale;
            float v2 = acc[mt][nt][2] * scale, v3 = acc[mt][nt][3] * scale;
            if (EPI == 0) {
                *(float2*)(Cf + (size_t)r * Nn + c) = make_float2(v0, v1);
                *(float2*)(Cf + (size_t)(r + 8) * Nn + c) = make_float2(v2, v3);
            } else {
                bf16 h0 = __float2bfloat16_rn(v0), h1 = __float2bfloat16_rn(v1);
                bf16 h2 = __float2bfloat16_rn(v2), h3 = __float2bfloat16_rn(v3);
                __nv_bfloat162 hp0; hp0.x = h0; hp0.y = h1;
                __nv_bfloat162 hp1; hp1.x = h2; hp1.y = h3;
                __nv_bfloat162 lp0, lp1;
                lp0.x = __float2bfloat16_rn(v0 - __bfloat162float(h0));
                lp0.y = __float2bfloat16_rn(v1 - __bfloat162float(h1));
                lp1.x = __float2bfloat16_rn(v2 - __bfloat162float(h2));
                lp1.y = __float2bfloat16_rn(v3 - __bfloat162float(h3));
                *(__nv_bfloat162*)(Ch + (size_t)r * Nn + c) = hp0;
                *(__nv_bfloat162*)(Ch + (size_t)(r + 8) * Nn + c) = hp1;
                *(__nv_bfloat162*)(Cl + (size_t)r * Nn + c) = lp0;
                *(__nv_bfloat162*)(Cl + (size_t)(r + 8) * Nn + c) = lp1;
            }
        }
    }
}

// ---------------- prep kernels ----------------
__global__ void split_pair(const float* __restrict__ src, bf16* __restrict__ h,
                           bf16* __restrict__ l, size_t n)
{
    size_t stride = (size_t)gridDim.x * blockDim.x * 4;
    for (size_t i = ((size_t)blockIdx.x * blockDim.x + threadIdx.x) * 4; i < n; i += stride) {
        float4 v = *(const float4*)(src + i);
        bf16 h0 = __float2bfloat16_rn(v.x), h1 = __float2bfloat16_rn(v.y);
        bf16 h2 = __float2bfloat16_rn(v.z), h3 = __float2bfloat16_rn(v.w);
        h[i + 0] = h0; h[i + 1] = h1; h[i + 2] = h2; h[i + 3] = h3;
        l[i + 0] = __float2bfloat16_rn(v.x - __bfloat162float(h0));
        l[i + 1] = __float2bfloat16_rn(v.y - __bfloat162float(h1));
        l[i + 2] = __float2bfloat16_rn(v.z - __bfloat162float(h2));
        l[i + 3] = __float2bfloat16_rn(v.w - __bfloat162float(h3));
    }
}

// transpose + split: src[R][C] fp32 -> th/tl[C][R] bf16
__global__ void tsplit(const float* __restrict__ src, bf16* __restrict__ th,
                       bf16* __restrict__ tl, int R, int C)
{
    __shared__ float buf[32][33];
    const int bx = blockIdx.x * 32;   // C offset
    const int by = blockIdx.y * 32;   // R offset
    const int t = threadIdx.x;
#pragma unroll
    for (int j = 0; j < 4; ++j) {
        int idx = t + 256 * j; int r = idx >> 5, c = idx & 31;
        buf[r][c] = src[(size_t)(by + r) * C + bx + c];
    }
    __syncthreads();
#pragma unroll
    for (int j = 0; j < 4; ++j) {
        int idx = t + 256 * j; int c = idx >> 5, r = idx & 31;
        float v = buf[r][c];
        size_t o = (size_t)(bx + c) * R + by + r;
        bf16 h = __float2bfloat16_rn(v);
        th[o] = h;
        tl[o] = __float2bfloat16_rn(v - __bfloat162float(h));
    }
}

// row softmax over S fp32, emit P as bf16 hi/lo pair. One block per row.
__global__ void __launch_bounds__(256) softmax_split(const float* __restrict__ S,
                                                     bf16* __restrict__ Ph,
                                                     bf16* __restrict__ Pl)
{
    __shared__ float buf[NTOK];
    __shared__ float red[8];
    const int row = blockIdx.x, t = threadIdx.x;
    const float* rp = S + (size_t)row * NTOK;

    float lmax = -INFINITY;
#pragma unroll
    for (int i = 0; i < 8; ++i) {
        int idx = (i * 256 + t) * 4;
        float4 v = *(const float4*)(rp + idx);
        *(float4*)(buf + idx) = v;
        lmax = fmaxf(lmax, fmaxf(fmaxf(v.x, v.y), fmaxf(v.z, v.w)));
    }
#pragma unroll
    for (int o = 16; o; o >>= 1) lmax = fmaxf(lmax, __shfl_xor_sync(0xffffffffu, lmax, o));
    if ((t & 31) == 0) red[t >> 5] = lmax;
    __syncthreads();
    float m = red[0];
#pragma unroll
    for (int i = 1; i < 8; ++i) m = fmaxf(m, red[i]);
    __syncthreads();

    float lsum = 0.f;
#pragma unroll
    for (int i = 0; i < 8; ++i) {
        int idx = (i * 256 + t) * 4;
        float4 v = *(const float4*)(buf + idx);
        v.x = __expf(v.x - m); v.y = __expf(v.y - m);
        v.z = __expf(v.z - m); v.w = __expf(v.w - m);
        lsum += (v.x + v.y) + (v.z + v.w);
        *(float4*)(buf + idx) = v;
    }
#pragma unroll
    for (int o = 16; o; o >>= 1) lsum += __shfl_xor_sync(0xffffffffu, lsum, o);
    if ((t & 31) == 0) red[t >> 5] = lsum;
    __syncthreads();
    float s = red[0];
#pragma unroll
    for (int i = 1; i < 8; ++i) s += red[i];
    const float inv = 1.f / s;

    bf16* ph = Ph + (size_t)row * NTOK;
    bf16* pl = Pl + (size_t)row * NTOK;
#pragma unroll
    for (int i = 0; i < 8; ++i) {
        int idx = (i * 256 + t) * 4;
        float4 v = *(const float4*)(buf + idx);
        float p0 = v.x * inv, p1 = v.y * inv, p2 = v.z * inv, p3 = v.w * inv;
        bf16 h0 = __float2bfloat16_rn(p0), h1 = __float2bfloat16_rn(p1);
        bf16 h2 = __float2bfloat16_rn(p2), h3 = __float2bfloat16_rn(p3);
        ph[idx] = h0; ph[idx + 1] = h1; ph[idx + 2] = h2; ph[idx + 3] = h3;
        pl[idx]     = __float2bfloat16_rn(p0 - __bfloat162float(h0));
        pl[idx + 1] = __float2bfloat16_rn(p1 - __bfloat162float(h1));
        pl[idx + 2] = __float2bfloat16_rn(p2 - __bfloat162float(h2));
        pl[idx + 3] = __float2bfloat16_rn(p3 - __bfloat162float(h3));
    }
}

// ---------------- launcher ----------------
extern "C" void kernel_launch(void* const* d_in, const int* in_sizes, int n_in,
                              void* d_out, int out_size)
{
    const float* x  = (const float*)d_in[0];
    const float* wq = (const float*)d_in[1];
    const float* wk = (const float*)d_in[2];
    const float* wv = (const float*)d_in[3];
    float* out = (float*)d_out;

    static bool inited = false;
    static float *S, *Vf;
    static bf16 *xh, *xl, *wqh, *wql, *wkh, *wkl, *wvh, *wvl;
    static bf16 *Qh, *Ql, *Kh, *Kl, *Vth, *Vtl, *Ph, *Pl;
    if (!inited) {
        inited = true;
        cudaFuncSetAttribute(gemm_nt<0>, cudaFuncAttributeMaxDynamicSharedMemorySize, DSM_BYTES);
        cudaFuncSetAttribute(gemm_nt<1>, cudaFuncAttributeMaxDynamicSharedMemorySize, DSM_BYTES);
        cudaGetSymbolAddress((void**)&S,   g_S);
        cudaGetSymbolAddress((void**)&Vf,  g_Vf);
        cudaGetSymbolAddress((void**)&xh,  g_xh);  cudaGetSymbolAddress((void**)&xl,  g_xl);
        cudaGetSymbolAddress((void**)&wqh, g_wqh); cudaGetSymbolAddress((void**)&wql, g_wql);
        cudaGetSymbolAddress((void**)&wkh, g_wkh); cudaGetSymbolAddress((void**)&wkl, g_wkl);
        cudaGetSymbolAddress((void**)&wvh, g_wvh); cudaGetSymbolAddress((void**)&wvl, g_wvl);
        cudaGetSymbolAddress((void**)&Qh,  g_Qh);  cudaGetSymbolAddress((void**)&Ql,  g_Ql);
        cudaGetSymbolAddress((void**)&Kh,  g_Kh);  cudaGetSymbolAddress((void**)&Kl,  g_Kl);
        cudaGetSymbolAddress((void**)&Vth, g_Vth); cudaGetSymbolAddress((void**)&Vtl, g_Vtl);
        cudaGetSymbolAddress((void**)&Ph,  g_Ph);  cudaGetSymbolAddress((void**)&Pl,  g_Pl);
    }

    // prep: split x; transpose+split weights
    split_pair<<<2048, 256>>>(x, xh, xl, (size_t)NTOK * DDIM);
    dim3 gW(DDIM / 32, DDIM / 32);
    tsplit<<<gW, 256>>>(wq, wqh, wql, DDIM, DDIM);
    tsplit<<<gW, 256>>>(wk, wkh, wkl, DDIM, DDIM);
    tsplit<<<gW, 256>>>(wv, wvh, wvl, DDIM, DDIM);

    // projections (NT vs transposed weights): [8192,1024] x [1024,1024]
    dim3 gProj(DDIM / 128, NTOK / 128);
    gemm_nt<1><<<gProj, 256, DSM_BYTES>>>(xh, xl, wqh, wql, nullptr, Qh, Ql, DDIM, DDIM, 1.f);
    gemm_nt<1><<<gProj, 256, DSM_BYTES>>>(xh, xl, wkh, wkl, nullptr, Kh, Kl, DDIM, DDIM, 1.f);
    gemm_nt<0><<<gProj, 256, DSM_BYTES>>>(xh, xl, wvh, wvl, Vf, nullptr, nullptr, DDIM, DDIM, 1.f);

    // V^T split for PV
    dim3 gV(DDIM / 32, NTOK / 32);
    tsplit<<<gV, 256>>>(Vf, Vth, Vtl, NTOK, DDIM);

    // scores: S = Q K^T / 32
    dim3 gS(NTOK / 128, NTOK / 128);
    gemm_nt<0><<<gS, 256, DSM_BYTES>>>(Qh, Ql, Kh, Kl, S, nullptr, nullptr, NTOK, DDIM, 0.03125f);

    // softmax -> split P
    softmax_split<<<NTOK, 256>>>(S, Ph, Pl);

    // out = P V
    dim3 gO(DDIM / 128, NTOK / 128);
    gemm_nt<0><<<gO, 256, DSM_BYTES>>>(Ph, Pl, Vth, Vtl, out, nullptr, nullptr, DDIM, NTOK, 1.f);
}

// round 12
// speedup vs baseline: 1.3076x; 1.0434x over previous
#include <cuda_runtime.h>
#include <cuda_bf16.h>
#include <cstdint>
#include <cmath>

#define NTOK 8192
#define DDIM 1024

typedef __nv_bfloat16 bf16;

// ---------------- scratch (allocation-free rule: __device__ globals) ----------------
__device__ float g_S [(size_t)NTOK * NTOK];
__device__ float g_Vf[(size_t)NTOK * DDIM];
__device__ bf16  g_xh[(size_t)NTOK * DDIM], g_xl[(size_t)NTOK * DDIM];
__device__ bf16  g_wqh[DDIM * DDIM], g_wql[DDIM * DDIM];   // transposed [n][k]
__device__ bf16  g_wkh[DDIM * DDIM], g_wkl[DDIM * DDIM];
__device__ bf16  g_wvh[DDIM * DDIM], g_wvl[DDIM * DDIM];
__device__ bf16  g_Qh[(size_t)NTOK * DDIM], g_Ql[(size_t)NTOK * DDIM];
__device__ bf16  g_Kh[(size_t)NTOK * DDIM], g_Kl[(size_t)NTOK * DDIM];
__device__ bf16  g_Vth[(size_t)DDIM * NTOK], g_Vtl[(size_t)DDIM * NTOK]; // [n][k]
__device__ bf16  g_Ph[(size_t)NTOK * NTOK], g_Pl[(size_t)NTOK * NTOK];

// ---------------- helpers ----------------
__device__ __forceinline__ uint32_t s2u(const void* p) {
    uint32_t a;
    asm("{ .reg .u64 t; cvta.to.shared.u64 t, %1; cvt.u32.u64 %0, t; }" : "=r"(a) : "l"(p));
    return a;
}
__device__ __forceinline__ void cp16(uint32_t dst, const void* src) {
    asm volatile("cp.async.cg.shared.global [%0], [%1], 16;" :: "r"(dst), "l"(src) : "memory");
}
__device__ __forceinline__ void cp_commit() { asm volatile("cp.async.commit_group;" ::: "memory"); }
template <int N>
__device__ __forceinline__ void cp_wait() { asm volatile("cp.async.wait_group %0;" :: "n"(N) : "memory"); }

__device__ __forceinline__ void mma_bf16(float c[4], const uint32_t a[4], const uint32_t b[2]) {
    asm volatile(
        "mma.sync.aligned.m16n8k16.row.col.f32.bf16.bf16.f32 "
        "{%0,%1,%2,%3}, {%4,%5,%6,%7}, {%8,%9}, {%0,%1,%2,%3};\n"
        : "+f"(c[0]), "+f"(c[1]), "+f"(c[2]), "+f"(c[3])
        : "r"(a[0]), "r"(a[1]), "r"(a[2]), "r"(a[3]), "r"(b[0]), "r"(b[1]));
}
__device__ __forceinline__ void ldsm_x4(uint32_t r[4], uint32_t addr) {
    asm volatile("ldmatrix.sync.aligned.m8n8.x4.shared.b16 {%0,%1,%2,%3}, [%4];"
                 : "=r"(r[0]), "=r"(r[1]), "=r"(r[2]), "=r"(r[3]) : "r"(addr));
}
__device__ __forceinline__ void ldsm_x2(uint32_t r[2], uint32_t addr) {
    asm volatile("ldmatrix.sync.aligned.m8n8.x2.shared.b16 {%0,%1}, [%2];"
                 : "=r"(r[0]), "=r"(r[1]) : "r"(addr));
}

// Block tile 128(M) x 64(N), 128 threads (4 warps, 2x2), warp tile 64x32.
// Stage: Ah[128][20], Al[128][20], Bh[64][20], Bl[64][20]  (16 payload + 4 pad words/row).
// Stride 20 words = 80B: 16B-granule index 5r mod 8 bijective -> LDSM conflict-free.
#define KM_STRIDE   20
#define AR_WORDS    (128 * KM_STRIDE)          // 2560
#define BR_WORDS    (64 * KM_STRIDE)           // 1280
#define STAGE_WORDS (2 * AR_WORDS + 2 * BR_WORDS)   // 7680
#define STAGE_BYTES (STAGE_WORDS * 4)          // 30720
#define NSTAGE      3
#define DSM_BYTES   (NSTAGE * STAGE_BYTES)     // 92160  -> 2 CTAs/SM

// C[M][Nn] = scale * (Ah+Al)[M][Kk] @ (Bh+Bl)[Nn][Kk]^T   (3-term split product)
// EPI=0: Cf fp32 out; EPI=1: Ch/Cl split-bf16 out. grid = (Nn/64, M/128), 128 threads.
template <int EPI>
__global__ void __launch_bounds__(128, 2)
gemm_nt(const bf16* __restrict__ Ah, const bf16* __restrict__ Al,
        const bf16* __restrict__ Bh, const bf16* __restrict__ Bl,
        float* __restrict__ Cf, bf16* __restrict__ Ch, bf16* __restrict__ Cl,
        int Nn, int Kk, float scale)
{
    extern __shared__ uint32_t smem[];
    const uint32_t sbase = s2u(smem);

    const int t = threadIdx.x;
    const int warp = t >> 5, lane = t & 31;
    const int bRow = blockIdx.y * 128, bCol = blockIdx.x * 64;
    const int wm = warp & 1;   // 2 warps along M -> 64-row warp tile
    const int wn = warp >> 1;  // 2 warps along N -> 32-col warp tile
    const int g = lane >> 2, tq = lane & 3;

    const bf16* gA[2] = { Ah + (size_t)bRow * Kk, Al + (size_t)bRow * Kk };
    const bf16* gB[2] = { Bh + (size_t)bCol * Kk, Bl + (size_t)bCol * Kk };
    const int cpRow = t >> 2, cpC = t & 3;      // row base (+k*32), 16B chunk

    // ldmatrix per-thread base offsets (bytes within a stage)
    uint32_t aOff[4], bOff[4];
#pragma unroll
    for (int mt = 0; mt < 4; ++mt)
        aOff[mt] = (uint32_t)(((wm * 64 + mt * 16 + (lane & 15)) * KM_STRIDE + (lane >> 4) * 4) * 4);
#pragma unroll
    for (int nt = 0; nt < 4; ++nt)
        bOff[nt] = (uint32_t)((2 * AR_WORDS + (wn * 32 + nt * 8 + (lane & 7)) * KM_STRIDE
                               + ((lane >> 3) & 1) * 4) * 4);
    const uint32_t loA = AR_WORDS * 4;   // Ah -> Al (bytes)
    const uint32_t loB = BR_WORDS * 4;   // Bh -> Bl (bytes)

    float acc[4][4][4];
#pragma unroll
    for (int i = 0; i < 4; ++i)
#pragma unroll
        for (int j = 0; j < 4; ++j)
#pragma unroll
            for (int k = 0; k < 4; ++k) acc[i][j][k] = 0.f;

    const int KT = Kk >> 5;   // 32-elem k-tiles

    auto copy_stage = [&](int s, int it) {
        const uint32_t sb = sbase + s * STAGE_BYTES;
        const int kOff = it * 32;
        // A arrays: 2 x 128 rows x 4 chunks = 1024 chunks -> 8/thread
#pragma unroll
        for (int j = 0; j < 8; ++j) {
            const int a = j >> 2;
            const int r = (j & 3) * 32 + cpRow;
            const bf16* src = gA[a] + (size_t)r * Kk + kOff + cpC * 8;
            uint32_t dst = sb + (uint32_t)((a * AR_WORDS + r * KM_STRIDE + cpC * 4) * 4);
            cp16(dst, src);
        }
        // B arrays: 2 x 64 rows x 4 chunks = 512 chunks -> 4/thread
#pragma unroll
        for (int j = 0; j < 4; ++j) {
            const int b = j >> 1;
            const int r = (j & 1) * 32 + cpRow;
            const bf16* src = gB[b] + (size_t)r * Kk + kOff + cpC * 8;
            uint32_t dst = sb + (uint32_t)((2 * AR_WORDS + b * BR_WORDS + r * KM_STRIDE + cpC * 4) * 4);
            cp16(dst, src);
        }
    };

    // Prologue: tiles 0 and 1 in flight (one commit group each).
    copy_stage(0, 0); cp_commit();
    copy_stage(1, 1); cp_commit();

    int stage = 0;
    for (int it = 0; it < KT; ++it) {
        cp_wait<1>();          // group for tile `it` complete (invariant: 2 groups out)
        __syncthreads();       // all warps done reading stage from iter it-1 + data visible

        // Refill: tile it+2 into the stage read at iter it-1 (safe after the sync).
        if (it + 2 < KT) {
            int ns = stage + 2; if (ns >= NSTAGE) ns -= NSTAGE;
            copy_stage(ns, it + 2);
        }
        cp_commit();           // dummy at tail keeps wait<1> semantics exact

        const uint32_t sb = sbase + stage * STAGE_BYTES;
#pragma unroll
        for (int ks2 = 0; ks2 < 16; ks2 += 8) {     // two k16 steps
            uint32_t ah[4][4], al[4][4], bh[4][2], bl[4][2];
#pragma unroll
            for (int mt = 0; mt < 4; ++mt) {
                uint32_t ad = sb + aOff[mt] + ks2 * 4;
                ldsm_x4(ah[mt], ad);
                ldsm_x4(al[mt], ad + loA);
            }
#pragma unroll
            for (int nt = 0; nt < 4; ++nt) {
                uint32_t bd = sb + bOff[nt] + ks2 * 4;
                ldsm_x2(bh[nt], bd);
                ldsm_x2(bl[nt], bd + loB);
            }
#pragma unroll
            for (int mt = 0; mt < 4; ++mt)
#pragma unroll
                for (int nt = 0; nt < 4; ++nt) {
                    mma_bf16(acc[mt][nt], ah[mt], bh[nt]);
                    mma_bf16(acc[mt][nt], ah[mt], bl[nt]);
                    mma_bf16(acc[mt][nt], al[mt], bh[nt]);
                }
        }
        if (++stage == NSTAGE) stage = 0;
    }

    // ---- epilogue: direct stores from accumulators ----
#pragma unroll
    for (int mt = 0; mt < 4; ++mt) {
#pragma unroll
        for (int nt = 0; nt < 4; ++nt) {
            int r = bRow + wm * 64 + mt * 16 + g;
            int c = bCol + wn * 32 + nt * 8 + tq * 2;
            float v0 = acc[mt][nt][0] * scale, v1 = acc[mt][nt][1] * scale;
            float v2 = acc[mt][nt][2] * scale, v3 = acc[mt][nt][3] * scale;
            if (EPI == 0) {
                *(float2*)(Cf + (size_t)r * Nn + c) = make_float2(v0, v1);
                *(float2*)(Cf + (size_t)(r + 8) * Nn + c) = make_float2(v2, v3);
            } else {
                bf16 h0 = __float2bfloat16_rn(v0), h1 = __float2bfloat16_rn(v1);
                bf16 h2 = __float2bfloat16_rn(v2), h3 = __float2bfloat16_rn(v3);
                __nv_bfloat162 hp0; hp0.x = h0; hp0.y = h1;
                __nv_bfloat162 hp1; hp1.x = h2; hp1.y = h3;
                __nv_bfloat162 lp0, lp1;
                lp0.x = __float2bfloat16_rn(v0 - __bfloat162float(h0));
                lp0.y = __float2bfloat16_rn(v1 - __bfloat162float(h1));
                lp1.x = __float2bfloat16_rn(v2 - __bfloat162float(h2));
                lp1.y = __float2bfloat16_rn(v3 - __bfloat162float(h3));
                *(__nv_bfloat162*)(Ch + (size_t)r * Nn + c) = hp0;
                *(__nv_bfloat162*)(Ch + (size_t)(r + 8) * Nn + c) = hp1;
                *(__nv_bfloat162*)(Cl + (size_t)r * Nn + c) = lp0;
                *(__nv_bfloat162*)(Cl + (size_t)(r + 8) * Nn + c) = lp1;
            }
        }
    }
}

// ---------------- prep kernels ----------------
__global__ void split_pair(const float* __restrict__ src, bf16* __restrict__ h,
                           bf16* __restrict__ l, size_t n)
{
    size_t stride = (size_t)gridDim.x * blockDim.x * 4;
    for (size_t i = ((size_t)blockIdx.x * blockDim.x + threadIdx.x) * 4; i < n; i += stride) {
        float4 v = *(const float4*)(src + i);
        bf16 h0 = __float2bfloat16_rn(v.x), h1 = __float2bfloat16_rn(v.y);
        bf16 h2 = __float2bfloat16_rn(v.z), h3 = __float2bfloat16_rn(v.w);
        h[i + 0] = h0; h[i + 1] = h1; h[i + 2] = h2; h[i + 3] = h3;
        l[i + 0] = __float2bfloat16_rn(v.x - __bfloat162float(h0));
        l[i + 1] = __float2bfloat16_rn(v.y - __bfloat162float(h1));
        l[i + 2] = __float2bfloat16_rn(v.z - __bfloat162float(h2));
        l[i + 3] = __float2bfloat16_rn(v.w - __bfloat162float(h3));
    }
}

// transpose + split: src[R][C] fp32 -> th/tl[C][R] bf16
__global__ void tsplit(const float* __restrict__ src, bf16* __restrict__ th,
                       bf16* __restrict__ tl, int R, int C)
{
    __shared__ float buf[32][33];
    const int bx = blockIdx.x * 32;   // C offset
    const int by = blockIdx.y * 32;   // R offset
    const int t = threadIdx.x;
#pragma unroll
    for (int j = 0; j < 4; ++j) {
        int idx = t + 256 * j; int r = idx >> 5, c = idx & 31;
        buf[r][c] = src[(size_t)(by + r) * C + bx + c];
    }
    __syncthreads();
#pragma unroll
    for (int j = 0; j < 4; ++j) {
        int idx = t + 256 * j; int c = idx >> 5, r = idx & 31;
        float v = buf[r][c];
        size_t o = (size_t)(bx + c) * R + by + r;
        bf16 h = __float2bfloat16_rn(v);
        th[o] = h;
        tl[o] = __float2bfloat16_rn(v - __bfloat162float(h));
    }
}

// row softmax over S fp32, emit P as bf16 hi/lo pair. One block per row.
__global__ void __launch_bounds__(256) softmax_split(const float* __restrict__ S,
                                                     bf16* __restrict__ Ph,
                                                     bf16* __restrict__ Pl)
{
    __shared__ float buf[NTOK];
    __shared__ float red[8];
    const int row = blockIdx.x, t = threadIdx.x;
    const float* rp = S + (size_t)row * NTOK;

    float lmax = -INFINITY;
#pragma unroll
    for (int i = 0; i < 8; ++i) {
        int idx = (i * 256 + t) * 4;
        float4 v = *(const float4*)(rp + idx);
        *(float4*)(buf + idx) = v;
        lmax = fmaxf(lmax, fmaxf(fmaxf(v.x, v.y), fmaxf(v.z, v.w)));
    }
#pragma unroll
    for (int o = 16; o; o >>= 1) lmax = fmaxf(lmax, __shfl_xor_sync(0xffffffffu, lmax, o));
    if ((t & 31) == 0) red[t >> 5] = lmax;
    __syncthreads();
    float m = red[0];
#pragma unroll
    for (int i = 1; i < 8; ++i) m = fmaxf(m, red[i]);
    __syncthreads();

    float lsum = 0.f;
#pragma unroll
    for (int i = 0; i < 8; ++i) {
        int idx = (i * 256 + t) * 4;
        float4 v = *(const float4*)(buf + idx);
        v.x = __expf(v.x - m); v.y = __expf(v.y - m);
        v.z = __expf(v.z - m); v.w = __expf(v.w - m);
        lsum += (v.x + v.y) + (v.z + v.w);
        *(float4*)(buf + idx) = v;
    }
#pragma unroll
    for (int o = 16; o; o >>= 1) lsum += __shfl_xor_sync(0xffffffffu, lsum, o);
    if ((t & 31) == 0) red[t >> 5] = lsum;
    __syncthreads();
    float s = red[0];
#pragma unroll
    for (int i = 1; i < 8; ++i) s += red[i];
    const float inv = 1.f / s;

    bf16* ph = Ph + (size_t)row * NTOK;
    bf16* pl = Pl + (size_t)row * NTOK;
#pragma unroll
    for (int i = 0; i < 8; ++i) {
        int idx = (i * 256 + t) * 4;
        float4 v = *(const float4*)(buf + idx);
        float p0 = v.x * inv, p1 = v.y * inv, p2 = v.z * inv, p3 = v.w * inv;
        bf16 h0 = __float2bfloat16_rn(p0), h1 = __float2bfloat16_rn(p1);
        bf16 h2 = __float2bfloat16_rn(p2), h3 = __float2bfloat16_rn(p3);
        ph[idx] = h0; ph[idx + 1] = h1; ph[idx + 2] = h2; ph[idx + 3] = h3;
        pl[idx]     = __float2bfloat16_rn(p0 - __bfloat162float(h0));
        pl[idx + 1] = __float2bfloat16_rn(p1 - __bfloat162float(h1));
        pl[idx + 2] = __float2bfloat16_rn(p2 - __bfloat162float(h2));
        pl[idx + 3] = __float2bfloat16_rn(p3 - __bfloat162float(h3));
    }
}

// ---------------- launcher ----------------
extern "C" void kernel_launch(void* const* d_in, const int* in_sizes, int n_in,
                              void* d_out, int out_size)
{
    const float* x  = (const float*)d_in[0];
    const float* wq = (const float*)d_in[1];
    const float* wk = (const float*)d_in[2];
    const float* wv = (const float*)d_in[3];
    float* out = (float*)d_out;

    static bool inited = false;
    static float *S, *Vf;
    static bf16 *xh, *xl, *wqh, *wql, *wkh, *wkl, *wvh, *wvl;
    static bf16 *Qh, *Ql, *Kh, *Kl, *Vth, *Vtl, *Ph, *Pl;
    if (!inited) {
        inited = true;
        cudaFuncSetAttribute(gemm_nt<0>, cudaFuncAttributeMaxDynamicSharedMemorySize, DSM_BYTES);
        cudaFuncSetAttribute(gemm_nt<1>, cudaFuncAttributeMaxDynamicSharedMemorySize, DSM_BYTES);
        cudaGetSymbolAddress((void**)&S,   g_S);
        cudaGetSymbolAddress((void**)&Vf,  g_Vf);
        cudaGetSymbolAddress((void**)&xh,  g_xh);  cudaGetSymbolAddress((void**)&xl,  g_xl);
        cudaGetSymbolAddress((void**)&wqh, g_wqh); cudaGetSymbolAddress((void**)&wql, g_wql);
        cudaGetSymbolAddress((void**)&wkh, g_wkh); cudaGetSymbolAddress((void**)&wkl, g_wkl);
        cudaGetSymbolAddress((void**)&wvh, g_wvh); cudaGetSymbolAddress((void**)&wvl, g_wvl);
        cudaGetSymbolAddress((void**)&Qh,  g_Qh);  cudaGetSymbolAddress((void**)&Ql,  g_Ql);
        cudaGetSymbolAddress((void**)&Kh,  g_Kh);  cudaGetSymbolAddress((void**)&Kl,  g_Kl);
        cudaGetSymbolAddress((void**)&Vth, g_Vth); cudaGetSymbolAddress((void**)&Vtl, g_Vtl);
        cudaGetSymbolAddress((void**)&Ph,  g_Ph);  cudaGetSymbolAddress((void**)&Pl,  g_Pl);
    }

    // prep: split x; transpose+split weights
    split_pair<<<2048, 256>>>(x, xh, xl, (size_t)NTOK * DDIM);
    dim3 gW(DDIM / 32, DDIM / 32);
    tsplit<<<gW, 256>>>(wq, wqh, wql, DDIM, DDIM);
    tsplit<<<gW, 256>>>(wk, wkh, wkl, DDIM, DDIM);
    tsplit<<<gW, 256>>>(wv, wvh, wvl, DDIM, DDIM);

    // projections (NT vs transposed weights): [8192,1024] x [1024,1024]
    dim3 gProj(DDIM / 64, NTOK / 128);
    gemm_nt<1><<<gProj, 128, DSM_BYTES>>>(xh, xl, wqh, wql, nullptr, Qh, Ql, DDIM, DDIM, 1.f);
    gemm_nt<1><<<gProj, 128, DSM_BYTES>>>(xh, xl, wkh, wkl, nullptr, Kh, Kl, DDIM, DDIM, 1.f);
    gemm_nt<0><<<gProj, 128, DSM_BYTES>>>(xh, xl, wvh, wvl, Vf, nullptr, nullptr, DDIM, DDIM, 1.f);

    // V^T split for PV
    dim3 gV(DDIM / 32, NTOK / 32);
    tsplit<<<gV, 256>>>(Vf, Vth, Vtl, NTOK, DDIM);

    // scores: S = Q K^T / 32
    dim3 gS(NTOK / 64, NTOK / 128);
    gemm_nt<0><<<gS, 128, DSM_BYTES>>>(Qh, Ql, Kh, Kl, S, nullptr, nullptr, NTOK, DDIM, 0.03125f);

    // softmax -> split P
    softmax_split<<<NTOK, 256>>>(S, Ph, Pl);

    // out = P V
    dim3 gO(DDIM / 64, NTOK / 128);
    gemm_nt<0><<<gO, 128, DSM_BYTES>>>(Ph, Pl, Vth, Vtl, out, nullptr, nullptr, DDIM, NTOK, 1.f);
}

// round 14
// speedup vs baseline: 1.4037x; 1.0735x over previous
#include <cuda_runtime.h>
#include <cuda_bf16.h>
#include <cstdint>
#include <cmath>

#define NTOK 8192
#define DDIM 1024

typedef __nv_bfloat16 bf16;

// ---------------- scratch (allocation-free rule: __device__ globals) ----------------
__device__ float g_S [(size_t)NTOK * NTOK];
__device__ float g_Vf[(size_t)NTOK * DDIM];
__device__ bf16  g_xh[(size_t)NTOK * DDIM], g_xl[(size_t)NTOK * DDIM];
__device__ bf16  g_wqh[DDIM * DDIM], g_wql[DDIM * DDIM];   // transposed [n][k]
__device__ bf16  g_wkh[DDIM * DDIM], g_wkl[DDIM * DDIM];
__device__ bf16  g_wvh[DDIM * DDIM], g_wvl[DDIM * DDIM];
__device__ bf16  g_Qh[(size_t)NTOK * DDIM], g_Ql[(size_t)NTOK * DDIM];
__device__ bf16  g_Kh[(size_t)NTOK * DDIM], g_Kl[(size_t)NTOK * DDIM];
__device__ bf16  g_Vth[(size_t)DDIM * NTOK], g_Vtl[(size_t)DDIM * NTOK]; // [n][k]
__device__ bf16  g_Ph[(size_t)NTOK * NTOK], g_Pl[(size_t)NTOK * NTOK];

// ---------------- helpers ----------------
__device__ __forceinline__ uint32_t s2u(const void* p) {
    uint32_t a;
    asm("{ .reg .u64 t; cvta.to.shared.u64 t, %1; cvt.u32.u64 %0, t; }" : "=r"(a) : "l"(p));
    return a;
}
__device__ __forceinline__ void cp16(uint32_t dst, const void* src) {
    asm volatile("cp.async.cg.shared.global [%0], [%1], 16;" :: "r"(dst), "l"(src) : "memory");
}
__device__ __forceinline__ void cp_commit() { asm volatile("cp.async.commit_group;" ::: "memory"); }
template <int N>
__device__ __forceinline__ void cp_wait() { asm volatile("cp.async.wait_group %0;" :: "n"(N) : "memory"); }

__device__ __forceinline__ void mma_bf16(float c[4], const uint32_t a[4], const uint32_t b[2]) {
    asm volatile(
        "mma.sync.aligned.m16n8k16.row.col.f32.bf16.bf16.f32 "
        "{%0,%1,%2,%3}, {%4,%5,%6,%7}, {%8,%9}, {%0,%1,%2,%3};\n"
        : "+f"(c[0]), "+f"(c[1]), "+f"(c[2]), "+f"(c[3])
        : "r"(a[0]), "r"(a[1]), "r"(a[2]), "r"(a[3]), "r"(b[0]), "r"(b[1]));
}
__device__ __forceinline__ void ldsm_x4(uint32_t r[4], uint32_t addr) {
    asm volatile("ldmatrix.sync.aligned.m8n8.x4.shared.b16 {%0,%1,%2,%3}, [%4];"
                 : "=r"(r[0]), "=r"(r[1]), "=r"(r[2]), "=r"(r[3]) : "r"(addr));
}

// Block tile 256(M) x 128(N), 256 threads (8 warps: 4 along M x 2 along N), warp tile 64x64.
// Stage arrays: Ah[256][20], Al[256][20], Bh[128][20], Bl[128][20] (16 payload + 4 pad words/row).
// Stride 20 words = 80B: 16B-granule index 5r mod 8 bijective -> LDSM conflict-free.
#define KM_STRIDE   20
#define AR_WORDS    (256 * KM_STRIDE)          // 5120
#define BR_WORDS    (128 * KM_STRIDE)          // 2560
#define STAGE_WORDS (2 * AR_WORDS + 2 * BR_WORDS)   // 15360
#define STAGE_BYTES (STAGE_WORDS * 4)          // 61440
#define NSTAGE      3
#define DSM_BYTES   (NSTAGE * STAGE_BYTES)     // 184320

// C[M][Nn] = scale * (Ah+Al)[M][Kk] @ (Bh+Bl)[Nn][Kk]^T   (3-term split product)
// EPI=0: Cf fp32 out; EPI=1: Ch/Cl split-bf16 out. grid = (Nn/128, M/256), 256 threads.
template <int EPI>
__global__ void __launch_bounds__(256, 1)
gemm_nt(const bf16* __restrict__ Ah, const bf16* __restrict__ Al,
        const bf16* __restrict__ Bh, const bf16* __restrict__ Bl,
        float* __restrict__ Cf, bf16* __restrict__ Ch, bf16* __restrict__ Cl,
        int Nn, int Kk, float scale)
{
    extern __shared__ uint32_t smem[];
    const uint32_t sbase = s2u(smem);

    const int t = threadIdx.x;
    const int warp = t >> 5, lane = t & 31;
    const int bRow = blockIdx.y * 256, bCol = blockIdx.x * 128;
    const int wm = warp & 3;   // 4 warps along M -> 64-row warp tile
    const int wn = warp >> 2;  // 2 warps along N -> 64-col warp tile
    const int g = lane >> 2, tq = lane & 3;

    const bf16* gA[2] = { Ah + (size_t)bRow * Kk, Al + (size_t)bRow * Kk };
    const bf16* gB[2] = { Bh + (size_t)bCol * Kk, Bl + (size_t)bCol * Kk };
    const int cpRow = t >> 2, cpC = t & 3;      // row base 0..63, 16B chunk

    // ldmatrix per-thread base offsets (bytes within a stage)
    // A (x4): lanes 0-15 rows m..m+15 @kw0, lanes 16-31 same rows @kw4.
    uint32_t aOff[4];
#pragma unroll
    for (int mt = 0; mt < 4; ++mt)
        aOff[mt] = (uint32_t)(((wm * 64 + mt * 16 + (lane & 15)) * KM_STRIDE + (lane >> 4) * 4) * 4);
    // B (x4, fused nt pair): mats = {rows n..n+7 @kw0, @kw4, rows n+8..n+15 @kw0, @kw4}
    uint32_t bOff[4];
#pragma unroll
    for (int np = 0; np < 4; ++np)
        bOff[np] = (uint32_t)((2 * AR_WORDS
                    + (wn * 64 + np * 16 + ((lane >> 4) & 1) * 8 + (lane & 7)) * KM_STRIDE
                    + ((lane >> 3) & 1) * 4) * 4);
    const uint32_t loA = AR_WORDS * 4;   // Ah -> Al (bytes)
    const uint32_t loB = BR_WORDS * 4;   // Bh -> Bl (bytes)

    float acc[4][8][4];
#pragma unroll
    for (int i = 0; i < 4; ++i)
#pragma unroll
        for (int j = 0; j < 8; ++j)
#pragma unroll
            for (int k = 0; k < 4; ++k) acc[i][j][k] = 0.f;

    const int KT = Kk >> 5;   // 32-elem k-tiles

    auto copy_stage = [&](int s, int it) {
        const uint32_t sb = sbase + s * STAGE_BYTES;
        const int kOff = it * 32;
        // A arrays: 2 x 256 rows x 4 chunks = 2048 chunks -> 8/thread
#pragma unroll
        for (int j = 0; j < 8; ++j) {
            const int a = j >> 2;
            const int r = (j & 3) * 64 + cpRow;
            const bf16* src = gA[a] + (size_t)r * Kk + kOff + cpC * 8;
            uint32_t dst = sb + (uint32_t)((a * AR_WORDS + r * KM_STRIDE + cpC * 4) * 4);
            cp16(dst, src);
        }
        // B arrays: 2 x 128 rows x 4 chunks = 1024 chunks -> 4/thread
#pragma unroll
        for (int j = 0; j < 4; ++j) {
            const int b = j >> 1;
            const int r = (j & 1) * 64 + cpRow;
            const bf16* src = gB[b] + (size_t)r * Kk + kOff + cpC * 8;
            uint32_t dst = sb + (uint32_t)((2 * AR_WORDS + b * BR_WORDS + r * KM_STRIDE + cpC * 4) * 4);
            cp16(dst, src);
        }
    };

    // Prologue: tiles 0 and 1 in flight (one commit group each).
    copy_stage(0, 0); cp_commit();
    copy_stage(1, 1); cp_commit();

    int stage = 0;
    for (int it = 0; it < KT; ++it) {
        cp_wait<1>();          // group for tile `it` complete (invariant: 2 groups out)
        __syncthreads();       // all warps done reading stage from iter it-1 + data visible

        // Refill: tile it+2 into the stage read at iter it-1 (safe after the sync).
        if (it + 2 < KT) {
            int ns = stage + 2; if (ns >= NSTAGE) ns -= NSTAGE;
            copy_stage(ns, it + 2);
        }
        cp_commit();           // dummy at tail keeps wait<1> semantics exact

        const uint32_t sb = sbase + stage * STAGE_BYTES;
#pragma unroll
        for (int ks2 = 0; ks2 < 16; ks2 += 8) {     // two k16 steps
            uint32_t ah[4][4], al[4][4], bh[8][2], bl[8][2];
#pragma unroll
            for (int mt = 0; mt < 4; ++mt) {
                uint32_t ad = sb + aOff[mt] + ks2 * 4;
                ldsm_x4(ah[mt], ad);
                ldsm_x4(al[mt], ad + loA);
            }
#pragma unroll
            for (int np = 0; np < 4; ++np) {
                uint32_t bd = sb + bOff[np] + ks2 * 4;
                uint32_t tmp[4];
                ldsm_x4(tmp, bd);
                bh[2 * np][0] = tmp[0]; bh[2 * np][1] = tmp[1];
                bh[2 * np + 1][0] = tmp[2]; bh[2 * np + 1][1] = tmp[3];
                ldsm_x4(tmp, bd + loB);
                bl[2 * np][0] = tmp[0]; bl[2 * np][1] = tmp[1];
                bl[2 * np + 1][0] = tmp[2]; bl[2 * np + 1][1] = tmp[3];
            }
#pragma unroll
            for (int mt = 0; mt < 4; ++mt)
#pragma unroll
                for (int nt = 0; nt < 8; ++nt) {
                    mma_bf16(acc[mt][nt], ah[mt], bh[nt]);
                    mma_bf16(acc[mt][nt], ah[mt], bl[nt]);
                    mma_bf16(acc[mt][nt], al[mt], bh[nt]);
                }
        }
        if (++stage == NSTAGE) stage = 0;
    }

    // ---- epilogue: direct stores from accumulators ----
#pragma unroll
    for (int mt = 0; mt < 4; ++mt) {
#pragma unroll
        for (int nt = 0; nt < 8; ++nt) {
            int r = bRow + wm * 64 + mt * 16 + g;
            int c = bCol + wn * 64 + nt * 8 + tq * 2;
            float v0 = acc[mt][nt][0] * scale, v1 = acc[mt][nt][1] * scale;
            float v2 = acc[mt][nt][2] * scale, v3 = acc[mt][nt][3] * scale;
            if (EPI == 0) {
                *(float2*)(Cf + (size_t)r * Nn + c) = make_float2(v0, v1);
                *(float2*)(Cf + (size_t)(r + 8) * Nn + c) = make_float2(v2, v3);
            } else {
                bf16 h0 = __float2bfloat16_rn(v0), h1 = __float2bfloat16_rn(v1);
                bf16 h2 = __float2bfloat16_rn(v2), h3 = __float2bfloat16_rn(v3);
                __nv_bfloat162 hp0; hp0.x = h0; hp0.y = h1;
                __nv_bfloat162 hp1; hp1.x = h2; hp1.y = h3;
                __nv_bfloat162 lp0, lp1;
                lp0.x = __float2bfloat16_rn(v0 - __bfloat162float(h0));
                lp0.y = __float2bfloat16_rn(v1 - __bfloat162float(h1));
                lp1.x = __float2bfloat16_rn(v2 - __bfloat162float(h2));
                lp1.y = __float2bfloat16_rn(v3 - __bfloat162float(h3));
                *(__nv_bfloat162*)(Ch + (size_t)r * Nn + c) = hp0;
                *(__nv_bfloat162*)(Ch + (size_t)(r + 8) * Nn + c) = hp1;
                *(__nv_bfloat162*)(Cl + (size_t)r * Nn + c) = lp0;
                *(__nv_bfloat162*)(Cl + (size_t)(r + 8) * Nn + c) = lp1;
            }
        }
    }
}

// ---------------- prep kernels ----------------
__global__ void split_pair(const float* __restrict__ src, bf16* __restrict__ h,
                           bf16* __restrict__ l, size_t n)
{
    size_t stride = (size_t)gridDim.x * blockDim.x * 4;
    for (size_t i = ((size_t)blockIdx.x * blockDim.x + threadIdx.x) * 4; i < n; i += stride) {
        float4 v = *(const float4*)(src + i);
        bf16 h0 = __float2bfloat16_rn(v.x), h1 = __float2bfloat16_rn(v.y);
        bf16 h2 = __float2bfloat16_rn(v.z), h3 = __float2bfloat16_rn(v.w);
        h[i + 0] = h0; h[i + 1] = h1; h[i + 2] = h2; h[i + 3] = h3;
        l[i + 0] = __float2bfloat16_rn(v.x - __bfloat162float(h0));
        l[i + 1] = __float2bfloat16_rn(v.y - __bfloat162float(h1));
        l[i + 2] = __float2bfloat16_rn(v.z - __bfloat162float(h2));
        l[i + 3] = __float2bfloat16_rn(v.w - __bfloat162float(h3));
    }
}

// transpose + split: src[R][C] fp32 -> th/tl[C][R] bf16
__global__ void tsplit(const float* __restrict__ src, bf16* __restrict__ th,
                       bf16* __restrict__ tl, int R, int C)
{
    __shared__ float buf[32][33];
    const int bx = blockIdx.x * 32;   // C offset
    const int by = blockIdx.y * 32;   // R offset
    const int t = threadIdx.x;
#pragma unroll
    for (int j = 0; j < 4; ++j) {
        int idx = t + 256 * j; int r = idx >> 5, c = idx & 31;
        buf[r][c] = src[(size_t)(by + r) * C + bx + c];
    }
    __syncthreads();
#pragma unroll
    for (int j = 0; j < 4; ++j) {
        int idx = t + 256 * j; int c = idx >> 5, r = idx & 31;
        float v = buf[r][c];
        size_t o = (size_t)(bx + c) * R + by + r;
        bf16 h = __float2bfloat16_rn(v);
        th[o] = h;
        tl[o] = __float2bfloat16_rn(v - __bfloat162float(h));
    }
}

// row softmax over S fp32, emit P as bf16 hi/lo pair. One block per row.
__global__ void __launch_bounds__(256) softmax_split(const float* __restrict__ S,
                                                     bf16* __restrict__ Ph,
                                                     bf16* __restrict__ Pl)
{
    __shared__ float buf[NTOK];
    __shared__ float red[8];
    const int row = blockIdx.x, t = threadIdx.x;
    const float* rp = S + (size_t)row * NTOK;

    float lmax = -INFINITY;
#pragma unroll
    for (int i = 0; i < 8; ++i) {
        int idx = (i * 256 + t) * 4;
        float4 v = *(const float4*)(rp + idx);
        *(float4*)(buf + idx) = v;
        lmax = fmaxf(lmax, fmaxf(fmaxf(v.x, v.y), fmaxf(v.z, v.w)));
    }
#pragma unroll
    for (int o = 16; o; o >>= 1) lmax = fmaxf(lmax, __shfl_xor_sync(0xffffffffu, lmax, o));
    if ((t & 31) == 0) red[t >> 5] = lmax;
    __syncthreads();
    float m = red[0];
#pragma unroll
    for (int i = 1; i < 8; ++i) m = fmaxf(m, red[i]);
    __syncthreads();

    float lsum = 0.f;
#pragma unroll
    for (int i = 0; i < 8; ++i) {
        int idx = (i * 256 + t) * 4;
        float4 v = *(const float4*)(buf + idx);
        v.x = __expf(v.x - m); v.y = __expf(v.y - m);
        v.z = __expf(v.z - m); v.w = __expf(v.w - m);
        lsum += (v.x + v.y) + (v.z + v.w);
        *(float4*)(buf + idx) = v;
    }
#pragma unroll
    for (int o = 16; o; o >>= 1) lsum += __shfl_xor_sync(0xffffffffu, lsum, o);
    if ((t & 31) == 0) red[t >> 5] = lsum;
    __syncthreads();
    float s = red[0];
#pragma unroll
    for (int i = 1; i < 8; ++i) s += red[i];
    const float inv = 1.f / s;

    bf16* ph = Ph + (size_t)row * NTOK;
    bf16* pl = Pl + (size_t)row * NTOK;
#pragma unroll
    for (int i = 0; i < 8; ++i) {
        int idx = (i * 256 + t) * 4;
        float4 v = *(const float4*)(buf + idx);
        float p0 = v.x * inv, p1 = v.y * inv, p2 = v.z * inv, p3 = v.w * inv;
        bf16 h0 = __float2bfloat16_rn(p0), h1 = __float2bfloat16_rn(p1);
        bf16 h2 = __float2bfloat16_rn(p2), h3 = __float2bfloat16_rn(p3);
        ph[idx] = h0; ph[idx + 1] = h1; ph[idx + 2] = h2; ph[idx + 3] = h3;
        pl[idx]     = __float2bfloat16_rn(p0 - __bfloat162float(h0));
        pl[idx + 1] = __float2bfloat16_rn(p1 - __bfloat162float(h1));
        pl[idx + 2] = __float2bfloat16_rn(p2 - __bfloat162float(h2));
        pl[idx + 3] = __float2bfloat16_rn(p3 - __bfloat162float(h3));
    }
}

// ---------------- launcher ----------------
extern "C" void kernel_launch(void* const* d_in, const int* in_sizes, int n_in,
                              void* d_out, int out_size)
{
    const float* x  = (const float*)d_in[0];
    const float* wq = (const float*)d_in[1];
    const float* wk = (const float*)d_in[2];
    const float* wv = (const float*)d_in[3];
    float* out = (float*)d_out;

    static bool inited = false;
    static float *S, *Vf;
    static bf16 *xh, *xl, *wqh, *wql, *wkh, *wkl, *wvh, *wvl;
    static bf16 *Qh, *Ql, *Kh, *Kl, *Vth, *Vtl, *Ph, *Pl;
    if (!inited) {
        inited = true;
        cudaFuncSetAttribute(gemm_nt<0>, cudaFuncAttributeMaxDynamicSharedMemorySize, DSM_BYTES);
        cudaFuncSetAttribute(gemm_nt<1>, cudaFuncAttributeMaxDynamicSharedMemorySize, DSM_BYTES);
        cudaGetSymbolAddress((void**)&S,   g_S);
        cudaGetSymbolAddress((void**)&Vf,  g_Vf);
        cudaGetSymbolAddress((void**)&xh,  g_xh);  cudaGetSymbolAddress((void**)&xl,  g_xl);
        cudaGetSymbolAddress((void**)&wqh, g_wqh); cudaGetSymbolAddress((void**)&wql, g_wql);
        cudaGetSymbolAddress((void**)&wkh, g_wkh); cudaGetSymbolAddress((void**)&wkl, g_wkl);
        cudaGetSymbolAddress((void**)&wvh, g_wvh); cudaGetSymbolAddress((void**)&wvl, g_wvl);
        cudaGetSymbolAddress((void**)&Qh,  g_Qh);  cudaGetSymbolAddress((void**)&Ql,  g_Ql);
        cudaGetSymbolAddress((void**)&Kh,  g_Kh);  cudaGetSymbolAddress((void**)&Kl,  g_Kl);
        cudaGetSymbolAddress((void**)&Vth, g_Vth); cudaGetSymbolAddress((void**)&Vtl, g_Vtl);
        cudaGetSymbolAddress((void**)&Ph,  g_Ph);  cudaGetSymbolAddress((void**)&Pl,  g_Pl);
    }

    // prep: split x; transpose+split weights
    split_pair<<<2048, 256>>>(x, xh, xl, (size_t)NTOK * DDIM);
    dim3 gW(DDIM / 32, DDIM / 32);
    tsplit<<<gW, 256>>>(wq, wqh, wql, DDIM, DDIM);
    tsplit<<<gW, 256>>>(wk, wkh, wkl, DDIM, DDIM);
    tsplit<<<gW, 256>>>(wv, wvh, wvl, DDIM, DDIM);

    // projections (NT vs transposed weights): [8192,1024] x [1024,1024]
    dim3 gProj(DDIM / 128, NTOK / 256);
    gemm_nt<1><<<gProj, 256, DSM_BYTES>>>(xh, xl, wqh, wql, nullptr, Qh, Ql, DDIM, DDIM, 1.f);
    gemm_nt<1><<<gProj, 256, DSM_BYTES>>>(xh, xl, wkh, wkl, nullptr, Kh, Kl, DDIM, DDIM, 1.f);
    gemm_nt<0><<<gProj, 256, DSM_BYTES>>>(xh, xl, wvh, wvl, Vf, nullptr, nullptr, DDIM, DDIM, 1.f);

    // V^T split for PV
    dim3 gV(DDIM / 32, NTOK / 32);
    tsplit<<<gV, 256>>>(Vf, Vth, Vtl, NTOK, DDIM);

    // scores: S = Q K^T / 32
    dim3 gS(NTOK / 128, NTOK / 256);
    gemm_nt<0><<<gS, 256, DSM_BYTES>>>(Qh, Ql, Kh, Kl, S, nullptr, nullptr, NTOK, DDIM, 0.03125f);

    // softmax -> split P
    softmax_split<<<NTOK, 256>>>(S, Ph, Pl);

    // out = P V
    dim3 gO(DDIM / 128, NTOK / 256);
    gemm_nt<0><<<gO, 256, DSM_BYTES>>>(Ph, Pl, Vth, Vtl, out, nullptr, nullptr, DDIM, NTOK, 1.f);
}

// round 15
// speedup vs baseline: 1.5262x; 1.0873x over previous
#include <cuda_runtime.h>
#include <cuda_bf16.h>
#include <cstdint>
#include <cmath>

#define NTOK 8192
#define DDIM 1024

typedef __nv_bfloat16 bf16;

// ---------------- scratch (allocation-free rule: __device__ globals) ----------------
__device__ float g_S [(size_t)NTOK * NTOK];
__device__ float g_Vf[(size_t)NTOK * DDIM];
__device__ bf16  g_xh[(size_t)NTOK * DDIM], g_xl[(size_t)NTOK * DDIM];
__device__ bf16  g_wqh[DDIM * DDIM], g_wql[DDIM * DDIM];   // transposed [n][k]
__device__ bf16  g_wkh[DDIM * DDIM], g_wkl[DDIM * DDIM];
__device__ bf16  g_wvh[DDIM * DDIM], g_wvl[DDIM * DDIM];
__device__ bf16  g_Qh[(size_t)NTOK * DDIM], g_Ql[(size_t)NTOK * DDIM];
__device__ bf16  g_Kh[(size_t)NTOK * DDIM], g_Kl[(size_t)NTOK * DDIM];
__device__ bf16  g_Vth[(size_t)DDIM * NTOK], g_Vtl[(size_t)DDIM * NTOK]; // [n][k]
__device__ bf16  g_Ph[(size_t)NTOK * NTOK], g_Pl[(size_t)NTOK * NTOK];

// ---------------- helpers ----------------
__device__ __forceinline__ uint32_t s2u(const void* p) {
    uint32_t a;
    asm("{ .reg .u64 t; cvta.to.shared.u64 t, %1; cvt.u32.u64 %0, t; }" : "=r"(a) : "l"(p));
    return a;
}
__device__ __forceinline__ void cp16(uint32_t dst, const void* src) {
    asm volatile("cp.async.cg.shared.global [%0], [%1], 16;" :: "r"(dst), "l"(src) : "memory");
}
__device__ __forceinline__ void cp_commit() { asm volatile("cp.async.commit_group;" ::: "memory"); }
template <int N>
__device__ __forceinline__ void cp_wait() { asm volatile("cp.async.wait_group %0;" :: "n"(N) : "memory"); }

__device__ __forceinline__ void mma_bf16(float c[4], const uint32_t a[4], const uint32_t b[2]) {
    asm volatile(
        "mma.sync.aligned.m16n8k16.row.col.f32.bf16.bf16.f32 "
        "{%0,%1,%2,%3}, {%4,%5,%6,%7}, {%8,%9}, {%0,%1,%2,%3};\n"
        : "+f"(c[0]), "+f"(c[1]), "+f"(c[2]), "+f"(c[3])
        : "r"(a[0]), "r"(a[1]), "r"(a[2]), "r"(a[3]), "r"(b[0]), "r"(b[1]));
}
__device__ __forceinline__ void ldsm_x4(uint32_t r[4], uint32_t addr) {
    asm volatile("ldmatrix.sync.aligned.m8n8.x4.shared.b16 {%0,%1,%2,%3}, [%4];"
                 : "=r"(r[0]), "=r"(r[1]), "=r"(r[2]), "=r"(r[3]) : "r"(addr));
}

// Block tile 256(M) x 128(N), 256 threads (8 warps: 4 along M x 2 along N), warp tile 64x64.
// K-tile = 64. Stage arrays: Ah[256][36], Al[256][36], Bh[128][36], Bl[128][36]
// (32 payload kwords + 4 pad words/row). Stride 36 words = 144B: 16B-granule index
// 9r mod 8 = r mod 8, bijective over 8 rows -> LDSM conflict-free.
#define KM_STRIDE   36
#define AR_WORDS    (256 * KM_STRIDE)          // 9216
#define BR_WORDS    (128 * KM_STRIDE)          // 4608
#define STAGE_WORDS (2 * AR_WORDS + 2 * BR_WORDS)   // 27648
#define STAGE_BYTES (STAGE_WORDS * 4)          // 110592
#define NSTAGE      2
#define DSM_BYTES   (NSTAGE * STAGE_BYTES)     // 221184

// C[M][Nn] = scale * (Ah+Al)[M][Kk] @ (Bh+Bl)[Nn][Kk]^T   (3-term split product)
// EPI=0: Cf fp32 out; EPI=1: Ch/Cl split-bf16 out. grid = (Nn/128, M/256), 256 threads.
// Requires Kk % 64 == 0.
template <int EPI>
__global__ void __launch_bounds__(256, 1)
gemm_nt(const bf16* __restrict__ Ah, const bf16* __restrict__ Al,
        const bf16* __restrict__ Bh, const bf16* __restrict__ Bl,
        float* __restrict__ Cf, bf16* __restrict__ Ch, bf16* __restrict__ Cl,
        int Nn, int Kk, float scale)
{
    extern __shared__ uint32_t smem[];
    const uint32_t sbase = s2u(smem);

    const int t = threadIdx.x;
    const int warp = t >> 5, lane = t & 31;
    const int bRow = blockIdx.y * 256, bCol = blockIdx.x * 128;
    const int wm = warp & 3;   // 4 warps along M -> 64-row warp tile
    const int wn = warp >> 2;  // 2 warps along N -> 64-col warp tile
    const int g = lane >> 2, tq = lane & 3;

    const bf16* gA[2] = { Ah + (size_t)bRow * Kk, Al + (size_t)bRow * Kk };
    const bf16* gB[2] = { Bh + (size_t)bCol * Kk, Bl + (size_t)bCol * Kk };
    const int cpRow = t >> 3, cpC = t & 7;      // row base 0..31, 16B chunk 0..7

    // ldmatrix per-thread base offsets (bytes within a stage)
    uint32_t aOff[4];
#pragma unroll
    for (int mt = 0; mt < 4; ++mt)
        aOff[mt] = (uint32_t)(((wm * 64 + mt * 16 + (lane & 15)) * KM_STRIDE + (lane >> 4) * 4) * 4);
    uint32_t bOff[4];
#pragma unroll
    for (int np = 0; np < 4; ++np)
        bOff[np] = (uint32_t)((2 * AR_WORDS
                    + (wn * 64 + np * 16 + ((lane >> 4) & 1) * 8 + (lane & 7)) * KM_STRIDE
                    + ((lane >> 3) & 1) * 4) * 4);
    const uint32_t loA = AR_WORDS * 4;   // Ah -> Al (bytes)
    const uint32_t loB = BR_WORDS * 4;   // Bh -> Bl (bytes)

    float acc[4][8][4];
#pragma unroll
    for (int i = 0; i < 4; ++i)
#pragma unroll
        for (int j = 0; j < 8; ++j)
#pragma unroll
            for (int k = 0; k < 4; ++k) acc[i][j][k] = 0.f;

    const int KT = Kk >> 6;   // 64-elem k-tiles

    auto copy_stage = [&](int s, int it) {
        const uint32_t sb = sbase + s * STAGE_BYTES;
        const int kOff = it * 64;
        // A arrays: 2 x 256 rows x 8 chunks = 4096 chunks -> 16/thread
#pragma unroll
        for (int j = 0; j < 16; ++j) {
            const int a = j >> 3;
            const int r = (j & 7) * 32 + cpRow;
            const bf16* src = gA[a] + (size_t)r * Kk + kOff + cpC * 8;
            uint32_t dst = sb + (uint32_t)((a * AR_WORDS + r * KM_STRIDE + cpC * 4) * 4);
            cp16(dst, src);
        }
        // B arrays: 2 x 128 rows x 8 chunks = 2048 chunks -> 8/thread
#pragma unroll
        for (int j = 0; j < 8; ++j) {
            const int b = j >> 2;
            const int r = (j & 3) * 32 + cpRow;
            const bf16* src = gB[b] + (size_t)r * Kk + kOff + cpC * 8;
            uint32_t dst = sb + (uint32_t)((2 * AR_WORDS + b * BR_WORDS + r * KM_STRIDE + cpC * 4) * 4);
            cp16(dst, src);
        }
    };

    // Prologue: tile 0 in flight.
    copy_stage(0, 0); cp_commit();

    for (int it = 0; it < KT; ++it) {
        cp_wait<0>();          // tile `it` copy complete (sole outstanding group)
        __syncthreads();       // data visible to all; stage (it+1)&1 fully consumed

        // Issue copy of tile it+1 into the other stage (overlaps MMAs below).
        if (it + 1 < KT) copy_stage((it + 1) & 1, it + 1);
        cp_commit();

        const uint32_t sb = sbase + (it & 1) * STAGE_BYTES;
#pragma unroll
        for (int ks2 = 0; ks2 < 32; ks2 += 8) {     // four k16 steps per 64-k tile
            uint32_t ah[4][4], al[4][4], bh[8][2], bl[8][2];
#pragma unroll
            for (int mt = 0; mt < 4; ++mt) {
                uint32_t ad = sb + aOff[mt] + ks2 * 4;
                ldsm_x4(ah[mt], ad);
                ldsm_x4(al[mt], ad + loA);
            }
#pragma unroll
            for (int np = 0; np < 4; ++np) {
                uint32_t bd = sb + bOff[np] + ks2 * 4;
                uint32_t tmp[4];
                ldsm_x4(tmp, bd);
                bh[2 * np][0] = tmp[0]; bh[2 * np][1] = tmp[1];
                bh[2 * np + 1][0] = tmp[2]; bh[2 * np + 1][1] = tmp[3];
                ldsm_x4(tmp, bd + loB);
                bl[2 * np][0] = tmp[0]; bl[2 * np][1] = tmp[1];
                bl[2 * np + 1][0] = tmp[2]; bl[2 * np + 1][1] = tmp[3];
            }
#pragma unroll
            for (int mt = 0; mt < 4; ++mt)
#pragma unroll
                for (int nt = 0; nt < 8; ++nt) {
                    mma_bf16(acc[mt][nt], ah[mt], bh[nt]);
                    mma_bf16(acc[mt][nt], ah[mt], bl[nt]);
                    mma_bf16(acc[mt][nt], al[mt], bh[nt]);
                }
        }
    }

    // ---- epilogue: direct stores from accumulators ----
#pragma unroll
    for (int mt = 0; mt < 4; ++mt) {
#pragma unroll
        for (int nt = 0; nt < 8; ++nt) {
            int r = bRow + wm * 64 + mt * 16 + g;
            int c = bCol + wn * 64 + nt * 8 + tq * 2;
            float v0 = acc[mt][nt][0] * scale, v1 = acc[mt][nt][1] * scale;
            float v2 = acc[mt][nt][2] * scale, v3 = acc[mt][nt][3] * scale;
            if (EPI == 0) {
                *(float2*)(Cf + (size_t)r * Nn + c) = make_float2(v0, v1);
                *(float2*)(Cf + (size_t)(r + 8) * Nn + c) = make_float2(v2, v3);
            } else {
                bf16 h0 = __float2bfloat16_rn(v0), h1 = __float2bfloat16_rn(v1);
                bf16 h2 = __float2bfloat16_rn(v2), h3 = __float2bfloat16_rn(v3);
                __nv_bfloat162 hp0; hp0.x = h0; hp0.y = h1;
                __nv_bfloat162 hp1; hp1.x = h2; hp1.y = h3;
                __nv_bfloat162 lp0, lp1;
                lp0.x = __float2bfloat16_rn(v0 - __bfloat162float(h0));
                lp0.y = __float2bfloat16_rn(v1 - __bfloat162float(h1));
                lp1.x = __float2bfloat16_rn(v2 - __bfloat162float(h2));
                lp1.y = __float2bfloat16_rn(v3 - __bfloat162float(h3));
                *(__nv_bfloat162*)(Ch + (size_t)r * Nn + c) = hp0;
                *(__nv_bfloat162*)(Ch + (size_t)(r + 8) * Nn + c) = hp1;
                *(__nv_bfloat162*)(Cl + (size_t)r * Nn + c) = lp0;
                *(__nv_bfloat162*)(Cl + (size_t)(r + 8) * Nn + c) = lp1;
            }
        }
    }
}

// ---------------- prep kernels ----------------
__global__ void split_pair(const float* __restrict__ src, bf16* __restrict__ h,
                           bf16* __restrict__ l, size_t n)
{
    size_t stride = (size_t)gridDim.x * blockDim.x * 4;
    for (size_t i = ((size_t)blockIdx.x * blockDim.x + threadIdx.x) * 4; i < n; i += stride) {
        float4 v = *(const float4*)(src + i);
        bf16 h0 = __float2bfloat16_rn(v.x), h1 = __float2bfloat16_rn(v.y);
        bf16 h2 = __float2bfloat16_rn(v.z), h3 = __float2bfloat16_rn(v.w);
        h[i + 0] = h0; h[i + 1] = h1; h[i + 2] = h2; h[i + 3] = h3;
        l[i + 0] = __float2bfloat16_rn(v.x - __bfloat162float(h0));
        l[i + 1] = __float2bfloat16_rn(v.y - __bfloat162float(h1));
        l[i + 2] = __float2bfloat16_rn(v.z - __bfloat162float(h2));
        l[i + 3] = __float2bfloat16_rn(v.w - __bfloat162float(h3));
    }
}

// transpose + split: src[R][C] fp32 -> th/tl[C][R] bf16
__global__ void tsplit(const float* __restrict__ src, bf16* __restrict__ th,
                       bf16* __restrict__ tl, int R, int C)
{
    __shared__ float buf[32][33];
    const int bx = blockIdx.x * 32;   // C offset
    const int by = blockIdx.y * 32;   // R offset
    const int t = threadIdx.x;
#pragma unroll
    for (int j = 0; j < 4; ++j) {
        int idx = t + 256 * j; int r = idx >> 5, c = idx & 31;
        buf[r][c] = src[(size_t)(by + r) * C + bx + c];
    }
    __syncthreads();
#pragma unroll
    for (int j = 0; j < 4; ++j) {
        int idx = t + 256 * j; int c = idx >> 5, r = idx & 31;
        float v = buf[r][c];
        size_t o = (size_t)(bx + c) * R + by + r;
        bf16 h = __float2bfloat16_rn(v);
        th[o] = h;
        tl[o] = __float2bfloat16_rn(v - __bfloat162float(h));
    }
}

// row softmax over S fp32, emit P as bf16 hi/lo pair. One block per row.
__global__ void __launch_bounds__(256) softmax_split(const float* __restrict__ S,
                                                     bf16* __restrict__ Ph,
                                                     bf16* __restrict__ Pl)
{
    __shared__ float buf[NTOK];
    __shared__ float red[8];
    const int row = blockIdx.x, t = threadIdx.x;
    const float* rp = S + (size_t)row * NTOK;

    float lmax = -INFINITY;
#pragma unroll
    for (int i = 0; i < 8; ++i) {
        int idx = (i * 256 + t) * 4;
        float4 v = *(const float4*)(rp + idx);
        *(float4*)(buf + idx) = v;
        lmax = fmaxf(lmax, fmaxf(fmaxf(v.x, v.y), fmaxf(v.z, v.w)));
    }
#pragma unroll
    for (int o = 16; o; o >>= 1) lmax = fmaxf(lmax, __shfl_xor_sync(0xffffffffu, lmax, o));
    if ((t & 31) == 0) red[t >> 5] = lmax;
    __syncthreads();
    float m = red[0];
#pragma unroll
    for (int i = 1; i < 8; ++i) m = fmaxf(m, red[i]);
    __syncthreads();

    float lsum = 0.f;
#pragma unroll
    for (int i = 0; i < 8; ++i) {
        int idx = (i * 256 + t) * 4;
        float4 v = *(const float4*)(buf + idx);
        v.x = __expf(v.x - m); v.y = __expf(v.y - m);
        v.z = __expf(v.z - m); v.w = __expf(v.w - m);
        lsum += (v.x + v.y) + (v.z + v.w);
        *(float4*)(buf + idx) = v;
    }
#pragma unroll
    for (int o = 16; o; o >>= 1) lsum += __shfl_xor_sync(0xffffffffu, lsum, o);
    if ((t & 31) == 0) red[t >> 5] = lsum;
    __syncthreads();
    float s = red[0];
#pragma unroll
    for (int i = 1; i < 8; ++i) s += red[i];
    const float inv = 1.f / s;

    bf16* ph = Ph + (size_t)row * NTOK;
    bf16* pl = Pl + (size_t)row * NTOK;
#pragma unroll
    for (int i = 0; i < 8; ++i) {
        int idx = (i * 256 + t) * 4;
        float4 v = *(const float4*)(buf + idx);
        float p0 = v.x * inv, p1 = v.y * inv, p2 = v.z * inv, p3 = v.w * inv;
        bf16 h0 = __float2bfloat16_rn(p0), h1 = __float2bfloat16_rn(p1);
        bf16 h2 = __float2bfloat16_rn(p2), h3 = __float2bfloat16_rn(p3);
        ph[idx] = h0; ph[idx + 1] = h1; ph[idx + 2] = h2; ph[idx + 3] = h3;
        pl[idx]     = __float2bfloat16_rn(p0 - __bfloat162float(h0));
        pl[idx + 1] = __float2bfloat16_rn(p1 - __bfloat162float(h1));
        pl[idx + 2] = __float2bfloat16_rn(p2 - __bfloat162float(h2));
        pl[idx + 3] = __float2bfloat16_rn(p3 - __bfloat162float(h3));
    }
}

// ---------------- launcher ----------------
extern "C" void kernel_launch(void* const* d_in, const int* in_sizes, int n_in,
                              void* d_out, int out_size)
{
    const float* x  = (const float*)d_in[0];
    const float* wq = (const float*)d_in[1];
    const float* wk = (const float*)d_in[2];
    const float* wv = (const float*)d_in[3];
    float* out = (float*)d_out;

    static bool inited = false;
    static float *S, *Vf;
    static bf16 *xh, *xl, *wqh, *wql, *wkh, *wkl, *wvh, *wvl;
    static bf16 *Qh, *Ql, *Kh, *Kl, *Vth, *Vtl, *Ph, *Pl;
    if (!inited) {
        inited = true;
        cudaFuncSetAttribute(gemm_nt<0>, cudaFuncAttributeMaxDynamicSharedMemorySize, DSM_BYTES);
        cudaFuncSetAttribute(gemm_nt<1>, cudaFuncAttributeMaxDynamicSharedMemorySize, DSM_BYTES);
        cudaGetSymbolAddress((void**)&S,   g_S);
        cudaGetSymbolAddress((void**)&Vf,  g_Vf);
        cudaGetSymbolAddress((void**)&xh,  g_xh);  cudaGetSymbolAddress((void**)&xl,  g_xl);
        cudaGetSymbolAddress((void**)&wqh, g_wqh); cudaGetSymbolAddress((void**)&wql, g_wql);
        cudaGetSymbolAddress((void**)&wkh, g_wkh); cudaGetSymbolAddress((void**)&wkl, g_wkl);
        cudaGetSymbolAddress((void**)&wvh, g_wvh); cudaGetSymbolAddress((void**)&wvl, g_wvl);
        cudaGetSymbolAddress((void**)&Qh,  g_Qh);  cudaGetSymbolAddress((void**)&Ql,  g_Ql);
        cudaGetSymbolAddress((void**)&Kh,  g_Kh);  cudaGetSymbolAddress((void**)&Kl,  g_Kl);
        cudaGetSymbolAddress((void**)&Vth, g_Vth); cudaGetSymbolAddress((void**)&Vtl, g_Vtl);
        cudaGetSymbolAddress((void**)&Ph,  g_Ph);  cudaGetSymbolAddress((void**)&Pl,  g_Pl);
    }

    // prep: split x; transpose+split weights
    split_pair<<<2048, 256>>>(x, xh, xl, (size_t)NTOK * DDIM);
    dim3 gW(DDIM / 32, DDIM / 32);
    tsplit<<<gW, 256>>>(wq, wqh, wql, DDIM, DDIM);
    tsplit<<<gW, 256>>>(wk, wkh, wkl, DDIM, DDIM);
    tsplit<<<gW, 256>>>(wv, wvh, wvl, DDIM, DDIM);

    // projections (NT vs transposed weights): [8192,1024] x [1024,1024]
    dim3 gProj(DDIM / 128, NTOK / 256);
    gemm_nt<1><<<gProj, 256, DSM_BYTES>>>(xh, xl, wqh, wql, nullptr, Qh, Ql, DDIM, DDIM, 1.f);
    gemm_nt<1><<<gProj, 256, DSM_BYTES>>>(xh, xl, wkh, wkl, nullptr, Kh, Kl, DDIM, DDIM, 1.f);
    gemm_nt<0><<<gProj, 256, DSM_BYTES>>>(xh, xl, wvh, wvl, Vf, nullptr, nullptr, DDIM, DDIM, 1.f);

    // V^T split for PV
    dim3 gV(DDIM / 32, NTOK / 32);
    tsplit<<<gV, 256>>>(Vf, Vth, Vtl, NTOK, DDIM);

    // scores: S = Q K^T / 32
    dim3 gS(NTOK / 128, NTOK / 256);
    gemm_nt<0><<<gS, 256, DSM_BYTES>>>(Qh, Ql, Kh, Kl, S, nullptr, nullptr, NTOK, DDIM, 0.03125f);

    // softmax -> split P
    softmax_split<<<NTOK, 256>>>(S, Ph, Pl);

    // out = P V
    dim3 gO(DDIM / 128, NTOK / 256);
    gemm_nt<0><<<gO, 256, DSM_BYTES>>>(Ph, Pl, Vth, Vtl, out, nullptr, nullptr, DDIM, NTOK, 1.f);
}

// round 16
// speedup vs baseline: 1.5270x; 1.0005x over previous
#include <cuda_runtime.h>
#include <cuda_bf16.h>
#include <cstdint>
#include <cmath>

#define NTOK 8192
#define DDIM 1024

typedef __nv_bfloat16 bf16;

// ---------------- scratch (allocation-free rule: __device__ globals) ----------------
__device__ float g_S [(size_t)NTOK * NTOK];
__device__ bf16  g_xh[(size_t)NTOK * DDIM], g_xl[(size_t)NTOK * DDIM];
__device__ bf16  g_wqh[DDIM * DDIM], g_wql[DDIM * DDIM];   // transposed [n][k]
__device__ bf16  g_wkh[DDIM * DDIM], g_wkl[DDIM * DDIM];
__device__ bf16  g_wvh[DDIM * DDIM], g_wvl[DDIM * DDIM];
__device__ bf16  g_Qh[(size_t)NTOK * DDIM], g_Ql[(size_t)NTOK * DDIM];
__device__ bf16  g_Kh[(size_t)NTOK * DDIM], g_Kl[(size_t)NTOK * DDIM];
__device__ bf16  g_Vth[(size_t)DDIM * NTOK], g_Vtl[(size_t)DDIM * NTOK]; // [n][k]
__device__ bf16  g_Ph[(size_t)NTOK * NTOK], g_Pl[(size_t)NTOK * NTOK];

// ---------------- helpers ----------------
__device__ __forceinline__ uint32_t s2u(const void* p) {
    uint32_t a;
    asm("{ .reg .u64 t; cvta.to.shared.u64 t, %1; cvt.u32.u64 %0, t; }" : "=r"(a) : "l"(p));
    return a;
}
__device__ __forceinline__ void cp16(uint32_t dst, const void* src) {
    asm volatile("cp.async.cg.shared.global [%0], [%1], 16;" :: "r"(dst), "l"(src) : "memory");
}
__device__ __forceinline__ void cp_commit() { asm volatile("cp.async.commit_group;" ::: "memory"); }
template <int N>
__device__ __forceinline__ void cp_wait() { asm volatile("cp.async.wait_group %0;" :: "n"(N) : "memory"); }

__device__ __forceinline__ void mma_bf16(float c[4], const uint32_t a[4], const uint32_t b[2]) {
    asm volatile(
        "mma.sync.aligned.m16n8k16.row.col.f32.bf16.bf16.f32 "
        "{%0,%1,%2,%3}, {%4,%5,%6,%7}, {%8,%9}, {%0,%1,%2,%3};\n"
        : "+f"(c[0]), "+f"(c[1]), "+f"(c[2]), "+f"(c[3])
        : "r"(a[0]), "r"(a[1]), "r"(a[2]), "r"(a[3]), "r"(b[0]), "r"(b[1]));
}
__device__ __forceinline__ void ldsm_x4(uint32_t r[4], uint32_t addr) {
    asm volatile("ldmatrix.sync.aligned.m8n8.x4.shared.b16 {%0,%1,%2,%3}, [%4];"
                 : "=r"(r[0]), "=r"(r[1]), "=r"(r[2]), "=r"(r[3]) : "r"(addr));
}

// Block tile 256(M) x 128(N), 256 threads (8 warps: 4 along M x 2 along N), warp tile 64x64.
// K-tile = 64. Stage arrays: Ah[256][36], Al[256][36], Bh[128][36], Bl[128][36]
// (32 payload kwords + 4 pad words/row). Stride 36 words = 144B: 16B-granule index
// 9r mod 8 = r mod 8, bijective over 8 rows -> LDSM conflict-free.
#define KM_STRIDE   36
#define AR_WORDS    (256 * KM_STRIDE)          // 9216
#define BR_WORDS    (128 * KM_STRIDE)          // 4608
#define STAGE_WORDS (2 * AR_WORDS + 2 * BR_WORDS)   // 27648
#define STAGE_BYTES (STAGE_WORDS * 4)          // 110592
#define NSTAGE      2
#define DSM_BYTES   (NSTAGE * STAGE_BYTES)     // 221184

#define TB_STRIDE   268    // epilogue transpose buffer stride (words); bank-safe

// C[M][Nn] = scale * (Ah+Al)[M][Kk] @ (Bh+Bl)[Nn][Kk]^T   (3-term split product)
// EPI=0: Cf fp32 out. EPI=1: Ch/Cl split-bf16 out (row-major [M][Nn]).
// EPI=2: Ch/Cl split-bf16 TRANSPOSED out [Nn][NTOK] (V path; M is NTOK).
// grid = (Nn/128, M/256), 256 threads. Requires Kk % 64 == 0.
template <int EPI>
__global__ void __launch_bounds__(256, 1)
gemm_nt(const bf16* __restrict__ Ah, const bf16* __restrict__ Al,
        const bf16* __restrict__ Bh, const bf16* __restrict__ Bl,
        float* __restrict__ Cf, bf16* __restrict__ Ch, bf16* __restrict__ Cl,
        int Nn, int Kk, float scale)
{
    extern __shared__ uint32_t smem[];
    const uint32_t sbase = s2u(smem);

    const int t = threadIdx.x;
    const int warp = t >> 5, lane = t & 31;
    const int bRow = blockIdx.y * 256, bCol = blockIdx.x * 128;
    const int wm = warp & 3;   // 4 warps along M -> 64-row warp tile
    const int wn = warp >> 2;  // 2 warps along N -> 64-col warp tile
    const int g = lane >> 2, tq = lane & 3;

    const bf16* gA[2] = { Ah + (size_t)bRow * Kk, Al + (size_t)bRow * Kk };
    const bf16* gB[2] = { Bh + (size_t)bCol * Kk, Bl + (size_t)bCol * Kk };
    const int cpRow = t >> 3, cpC = t & 7;      // row base 0..31, 16B chunk 0..7

    // ldmatrix per-thread base offsets (bytes within a stage)
    uint32_t aOff[4];
#pragma unroll
    for (int mt = 0; mt < 4; ++mt)
        aOff[mt] = (uint32_t)(((wm * 64 + mt * 16 + (lane & 15)) * KM_STRIDE + (lane >> 4) * 4) * 4);
    uint32_t bOff[4];
#pragma unroll
    for (int np = 0; np < 4; ++np)
        bOff[np] = (uint32_t)((2 * AR_WORDS
                    + (wn * 64 + np * 16 + ((lane >> 4) & 1) * 8 + (lane & 7)) * KM_STRIDE
                    + ((lane >> 3) & 1) * 4) * 4);
    const uint32_t loA = AR_WORDS * 4;   // Ah -> Al (bytes)
    const uint32_t loB = BR_WORDS * 4;   // Bh -> Bl (bytes)

    float acc[4][8][4];
#pragma unroll
    for (int i = 0; i < 4; ++i)
#pragma unroll
        for (int j = 0; j < 8; ++j)
#pragma unroll
            for (int k = 0; k < 4; ++k) acc[i][j][k] = 0.f;

    const int KT = Kk >> 6;   // 64-elem k-tiles

    auto copy_stage = [&](int s, int it) {
        const uint32_t sb = sbase + s * STAGE_BYTES;
        const int kOff = it * 64;
#pragma unroll
        for (int j = 0; j < 16; ++j) {
            const int a = j >> 3;
            const int r = (j & 7) * 32 + cpRow;
            const bf16* src = gA[a] + (size_t)r * Kk + kOff + cpC * 8;
            uint32_t dst = sb + (uint32_t)((a * AR_WORDS + r * KM_STRIDE + cpC * 4) * 4);
            cp16(dst, src);
        }
#pragma unroll
        for (int j = 0; j < 8; ++j) {
            const int b = j >> 2;
            const int r = (j & 3) * 32 + cpRow;
            const bf16* src = gB[b] + (size_t)r * Kk + kOff + cpC * 8;
            uint32_t dst = sb + (uint32_t)((2 * AR_WORDS + b * BR_WORDS + r * KM_STRIDE + cpC * 4) * 4);
            cp16(dst, src);
        }
    };

    // Prologue: tile 0 in flight.
    copy_stage(0, 0); cp_commit();

    for (int it = 0; it < KT; ++it) {
        cp_wait<0>();          // tile `it` copy complete (sole outstanding group)
        __syncthreads();       // data visible; other stage fully consumed

        if (it + 1 < KT) copy_stage((it + 1) & 1, it + 1);
        cp_commit();

        const uint32_t sb = sbase + (it & 1) * STAGE_BYTES;
#pragma unroll
        for (int ks2 = 0; ks2 < 32; ks2 += 8) {     // four k16 steps per 64-k tile
            uint32_t ah[4][4], al[4][4], bh[8][2], bl[8][2];
#pragma unroll
            for (int mt = 0; mt < 4; ++mt) {
                uint32_t ad = sb + aOff[mt] + ks2 * 4;
                ldsm_x4(ah[mt], ad);
                ldsm_x4(al[mt], ad + loA);
            }
#pragma unroll
            for (int np = 0; np < 4; ++np) {
                uint32_t bd = sb + bOff[np] + ks2 * 4;
                uint32_t tmp[4];
                ldsm_x4(tmp, bd);
                bh[2 * np][0] = tmp[0]; bh[2 * np][1] = tmp[1];
                bh[2 * np + 1][0] = tmp[2]; bh[2 * np + 1][1] = tmp[3];
                ldsm_x4(tmp, bd + loB);
                bl[2 * np][0] = tmp[0]; bl[2 * np][1] = tmp[1];
                bl[2 * np + 1][0] = tmp[2]; bl[2 * np + 1][1] = tmp[3];
            }
#pragma unroll
            for (int mt = 0; mt < 4; ++mt)
#pragma unroll
                for (int nt = 0; nt < 8; ++nt) {
                    mma_bf16(acc[mt][nt], ah[mt], bh[nt]);
                    mma_bf16(acc[mt][nt], ah[mt], bl[nt]);
                    mma_bf16(acc[mt][nt], al[mt], bh[nt]);
                }
        }
    }

    if (EPI == 2) {
        // ---- transposed split epilogue (V path): SMEM transpose, out [Nn][NTOK] ----
        __syncthreads();                 // all warps done with stage SMEM
        float* tb = (float*)smem;        // [128 c][TB_STRIDE r] fp32 = 137 KB < 216 KB
#pragma unroll
        for (int mt = 0; mt < 4; ++mt) {
#pragma unroll
            for (int nt = 0; nt < 8; ++nt) {
                int r = wm * 64 + mt * 16 + g;
                int c = wn * 64 + nt * 8 + tq * 2;
                tb[(c + 0) * TB_STRIDE + r]     = acc[mt][nt][0];
                tb[(c + 1) * TB_STRIDE + r]     = acc[mt][nt][1];
                tb[(c + 0) * TB_STRIDE + r + 8] = acc[mt][nt][2];
                tb[(c + 1) * TB_STRIDE + r + 8] = acc[mt][nt][3];
            }
        }
        __syncthreads();
#pragma unroll 4
        for (int c = 0; c < 128; ++c) {
            float v = tb[c * TB_STRIDE + t];
            bf16 h = __float2bfloat16_rn(v);
            size_t o = (size_t)(bCol + c) * NTOK + bRow + t;
            Ch[o] = h;
            Cl[o] = __float2bfloat16_rn(v - __bfloat162float(h));
        }
        return;
    }

    // ---- row-major epilogues: direct stores from accumulators ----
#pragma unroll
    for (int mt = 0; mt < 4; ++mt) {
#pragma unroll
        for (int nt = 0; nt < 8; ++nt) {
            int r = bRow + wm * 64 + mt * 16 + g;
            int c = bCol + wn * 64 + nt * 8 + tq * 2;
            float v0 = acc[mt][nt][0] * scale, v1 = acc[mt][nt][1] * scale;
            float v2 = acc[mt][nt][2] * scale, v3 = acc[mt][nt][3] * scale;
            if (EPI == 0) {
                *(float2*)(Cf + (size_t)r * Nn + c) = make_float2(v0, v1);
                *(float2*)(Cf + (size_t)(r + 8) * Nn + c) = make_float2(v2, v3);
            } else {
                bf16 h0 = __float2bfloat16_rn(v0), h1 = __float2bfloat16_rn(v1);
                bf16 h2 = __float2bfloat16_rn(v2), h3 = __float2bfloat16_rn(v3);
                __nv_bfloat162 hp0; hp0.x = h0; hp0.y = h1;
                __nv_bfloat162 hp1; hp1.x = h2; hp1.y = h3;
                __nv_bfloat162 lp0, lp1;
                lp0.x = __float2bfloat16_rn(v0 - __bfloat162float(h0));
                lp0.y = __float2bfloat16_rn(v1 - __bfloat162float(h1));
                lp1.x = __float2bfloat16_rn(v2 - __bfloat162float(h2));
                lp1.y = __float2bfloat16_rn(v3 - __bfloat162float(h3));
                *(__nv_bfloat162*)(Ch + (size_t)r * Nn + c) = hp0;
                *(__nv_bfloat162*)(Ch + (size_t)(r + 8) * Nn + c) = hp1;
                *(__nv_bfloat162*)(Cl + (size_t)r * Nn + c) = lp0;
                *(__nv_bfloat162*)(Cl + (size_t)(r + 8) * Nn + c) = lp1;
            }
        }
    }
}

// ---------------- prep kernels ----------------
__global__ void split_pair(const float* __restrict__ src, bf16* __restrict__ h,
                           bf16* __restrict__ l, size_t n)
{
    size_t stride = (size_t)gridDim.x * blockDim.x * 4;
    for (size_t i = ((size_t)blockIdx.x * blockDim.x + threadIdx.x) * 4; i < n; i += stride) {
        float4 v = *(const float4*)(src + i);
        bf16 h0 = __float2bfloat16_rn(v.x), h1 = __float2bfloat16_rn(v.y);
        bf16 h2 = __float2bfloat16_rn(v.z), h3 = __float2bfloat16_rn(v.w);
        h[i + 0] = h0; h[i + 1] = h1; h[i + 2] = h2; h[i + 3] = h3;
        l[i + 0] = __float2bfloat16_rn(v.x - __bfloat162float(h0));
        l[i + 1] = __float2bfloat16_rn(v.y - __bfloat162float(h1));
        l[i + 2] = __float2bfloat16_rn(v.z - __bfloat162float(h2));
        l[i + 3] = __float2bfloat16_rn(v.w - __bfloat162float(h3));
    }
}

// transpose + split for all 3 weight matrices in one launch (z selects matrix).
__global__ void tsplit_w(const float* __restrict__ wq, const float* __restrict__ wk,
                         const float* __restrict__ wv,
                         bf16* __restrict__ qh, bf16* __restrict__ ql,
                         bf16* __restrict__ kh, bf16* __restrict__ kl,
                         bf16* __restrict__ vh, bf16* __restrict__ vl)
{
    __shared__ float buf[32][33];
    const int bx = blockIdx.x * 32;   // C offset (output col -> input col)
    const int by = blockIdx.y * 32;   // R offset
    const int t = threadIdx.x;
    const float* src = (blockIdx.z == 0) ? wq : (blockIdx.z == 1) ? wk : wv;
    bf16* th = (blockIdx.z == 0) ? qh : (blockIdx.z == 1) ? kh : vh;
    bf16* tl = (blockIdx.z == 0) ? ql : (blockIdx.z == 1) ? kl : vl;
#pragma unroll
    for (int j = 0; j < 4; ++j) {
        int idx = t + 256 * j; int r = idx >> 5, c = idx & 31;
        buf[r][c] = src[(size_t)(by + r) * DDIM + bx + c];
    }
    __syncthreads();
#pragma unroll
    for (int j = 0; j < 4; ++j) {
        int idx = t + 256 * j; int c = idx >> 5, r = idx & 31;
        float v = buf[r][c];
        size_t o = (size_t)(bx + c) * DDIM + by + r;
        bf16 h = __float2bfloat16_rn(v);
        th[o] = h;
        tl[o] = __float2bfloat16_rn(v - __bfloat162float(h));
    }
}

// row softmax over S fp32, emit P as bf16 hi/lo pair. One block per row.
__global__ void __launch_bounds__(256) softmax_split(const float* __restrict__ S,
                                                     bf16* __restrict__ Ph,
                                                     bf16* __restrict__ Pl)
{
    __shared__ float buf[NTOK];
    __shared__ float red[8];
    const int row = blockIdx.x, t = threadIdx.x;
    const float* rp = S + (size_t)row * NTOK;

    float lmax = -INFINITY;
#pragma unroll
    for (int i = 0; i < 8; ++i) {
        int idx = (i * 256 + t) * 4;
        float4 v = *(const float4*)(rp + idx);
        *(float4*)(buf + idx) = v;
        lmax = fmaxf(lmax, fmaxf(fmaxf(v.x, v.y), fmaxf(v.z, v.w)));
    }
#pragma unroll
    for (int o = 16; o; o >>= 1) lmax = fmaxf(lmax, __shfl_xor_sync(0xffffffffu, lmax, o));
    if ((t & 31) == 0) red[t >> 5] = lmax;
    __syncthreads();
    float m = red[0];
#pragma unroll
    for (int i = 1; i < 8; ++i) m = fmaxf(m, red[i]);
    __syncthreads();

    float lsum = 0.f;
#pragma unroll
    for (int i = 0; i < 8; ++i) {
        int idx = (i * 256 + t) * 4;
        float4 v = *(const float4*)(buf + idx);
        v.x = __expf(v.x - m); v.y = __expf(v.y - m);
        v.z = __expf(v.z - m); v.w = __expf(v.w - m);
        lsum += (v.x + v.y) + (v.z + v.w);
        *(float4*)(buf + idx) = v;
    }
#pragma unroll
    for (int o = 16; o; o >>= 1) lsum += __shfl_xor_sync(0xffffffffu, lsum, o);
    if ((t & 31) == 0) red[t >> 5] = lsum;
    __syncthreads();
    float s = red[0];
#pragma unroll
    for (int i = 1; i < 8; ++i) s += red[i];
    const float inv = 1.f / s;

    bf16* ph = Ph + (size_t)row * NTOK;
    bf16* pl = Pl + (size_t)row * NTOK;
#pragma unroll
    for (int i = 0; i < 8; ++i) {
        int idx = (i * 256 + t) * 4;
        float4 v = *(const float4*)(buf + idx);
        float p0 = v.x * inv, p1 = v.y * inv, p2 = v.z * inv, p3 = v.w * inv;
        bf16 h0 = __float2bfloat16_rn(p0), h1 = __float2bfloat16_rn(p1);
        bf16 h2 = __float2bfloat16_rn(p2), h3 = __float2bfloat16_rn(p3);
        ph[idx] = h0; ph[idx + 1] = h1; ph[idx + 2] = h2; ph[idx + 3] = h3;
        pl[idx]     = __float2bfloat16_rn(p0 - __bfloat162float(h0));
        pl[idx + 1] = __float2bfloat16_rn(p1 - __bfloat162float(h1));
        pl[idx + 2] = __float2bfloat16_rn(p2 - __bfloat162float(h2));
        pl[idx + 3] = __float2bfloat16_rn(p3 - __bfloat162float(h3));
    }
}

// ---------------- launcher ----------------
extern "C" void kernel_launch(void* const* d_in, const int* in_sizes, int n_in,
                              void* d_out, int out_size)
{
    const float* x  = (const float*)d_in[0];
    const float* wq = (const float*)d_in[1];
    const float* wk = (const float*)d_in[2];
    const float* wv = (const float*)d_in[3];
    float* out = (float*)d_out;

    static bool inited = false;
    static float *S;
    static bf16 *xh, *xl, *wqh, *wql, *wkh, *wkl, *wvh, *wvl;
    static bf16 *Qh, *Ql, *Kh, *Kl, *Vth, *Vtl, *Ph, *Pl;
    if (!inited) {
        inited = true;
        cudaFuncSetAttribute(gemm_nt<0>, cudaFuncAttributeMaxDynamicSharedMemorySize, DSM_BYTES);
        cudaFuncSetAttribute(gemm_nt<1>, cudaFuncAttributeMaxDynamicSharedMemorySize, DSM_BYTES);
        cudaFuncSetAttribute(gemm_nt<2>, cudaFuncAttributeMaxDynamicSharedMemorySize, DSM_BYTES);
        cudaGetSymbolAddress((void**)&S,   g_S);
        cudaGetSymbolAddress((void**)&xh,  g_xh);  cudaGetSymbolAddress((void**)&xl,  g_xl);
        cudaGetSymbolAddress((void**)&wqh, g_wqh); cudaGetSymbolAddress((void**)&wql, g_wql);
        cudaGetSymbolAddress((void**)&wkh, g_wkh); cudaGetSymbolAddress((void**)&wkl, g_wkl);
        cudaGetSymbolAddress((void**)&wvh, g_wvh); cudaGetSymbolAddress((void**)&wvl, g_wvl);
        cudaGetSymbolAddress((void**)&Qh,  g_Qh);  cudaGetSymbolAddress((void**)&Ql,  g_Ql);
        cudaGetSymbolAddress((void**)&Kh,  g_Kh);  cudaGetSymbolAddress((void**)&Kl,  g_Kl);
        cudaGetSymbolAddress((void**)&Vth, g_Vth); cudaGetSymbolAddress((void**)&Vtl, g_Vtl);
        cudaGetSymbolAddress((void**)&Ph,  g_Ph);  cudaGetSymbolAddress((void**)&Pl,  g_Pl);
    }

    // prep: split x; transpose+split all three weights in one launch
    split_pair<<<2048, 256>>>(x, xh, xl, (size_t)NTOK * DDIM);
    dim3 gW(DDIM / 32, DDIM / 32, 3);
    tsplit_w<<<gW, 256>>>(wq, wk, wv, wqh, wql, wkh, wkl, wvh, wvl);

    // projections (NT vs transposed weights): [8192,1024] x [1024,1024]
    dim3 gProj(DDIM / 128, NTOK / 256);
    gemm_nt<1><<<gProj, 256, DSM_BYTES>>>(xh, xl, wqh, wql, nullptr, Qh, Ql, DDIM, DDIM, 1.f);
    gemm_nt<1><<<gProj, 256, DSM_BYTES>>>(xh, xl, wkh, wkl, nullptr, Kh, Kl, DDIM, DDIM, 1.f);
    // V projection with fused transpose-split epilogue -> Vt [dim][token]
    gemm_nt<2><<<gProj, 256, DSM_BYTES>>>(xh, xl, wvh, wvl, nullptr, Vth, Vtl, DDIM, DDIM, 1.f);

    // scores: S = Q K^T / 32
    dim3 gS(NTOK / 128, NTOK / 256);
    gemm_nt<0><<<gS, 256, DSM_BYTES>>>(Qh, Ql, Kh, Kl, S, nullptr, nullptr, NTOK, DDIM, 0.03125f);

    // softmax -> split P
    softmax_split<<<NTOK, 256>>>(S, Ph, Pl);

    // out = P V
    dim3 gO(DDIM / 128, NTOK / 256);
    gemm_nt<0><<<gO, 256, DSM_BYTES>>>(Ph, Pl, Vth, Vtl, out, nullptr, nullptr, DDIM, NTOK, 1.f);
}